// round 10
// baseline (speedup 1.0000x reference)
#include <cuda_runtime.h>
#include <cuda_bf16.h>
#include <cstdint>

typedef unsigned int u32;
typedef unsigned long long u64;
typedef unsigned short u16;

#define GG 3
#define ZCAP 4096
#define ST 136                 // bf16 elements per padded tile row (272 B)
#define TILEB (128*ST*2)       // 34816 bytes per 128x128 bf16 tile
#define DYNSM (6*TILEB)        // 208896
#define K4SMEM (3*128*129*4)   // 198144

// ---------------- device scratch (allocation-free) ----------------
__device__ float g_T1[16384];
__device__ float g_T2[16384];
__device__ int   g_znum[24];
__device__ int   g_zcnt[24*512];
__device__ int2  g_zlist[24*ZCAP];

// ---------------- helpers ----------------
static __device__ __forceinline__ u32 smem_u32(const void* p){
    u32 a;
    asm("{ .reg .u64 t; cvta.to.shared.u64 t, %1; cvt.u32.u64 %0, t; }" : "=r"(a) : "l"(p));
    return a;
}
#define LDSM_X4(r, a) \
    asm volatile("ldmatrix.sync.aligned.m8n8.x4.shared.b16 {%0,%1,%2,%3}, [%4];" \
        : "=r"((r)[0]),"=r"((r)[1]),"=r"((r)[2]),"=r"((r)[3]) : "r"(a))
#define LDSM_X4_T(r, a) \
    asm volatile("ldmatrix.sync.aligned.m8n8.x4.trans.shared.b16 {%0,%1,%2,%3}, [%4];" \
        : "=r"((r)[0]),"=r"((r)[1]),"=r"((r)[2]),"=r"((r)[3]) : "r"(a))

static __device__ __forceinline__ void mma16816(float* c, const u32* a, const u32* b){
    asm volatile("mma.sync.aligned.m16n8k16.row.col.f32.bf16.bf16.f32 "
        "{%0,%1,%2,%3}, {%4,%5,%6,%7}, {%8,%9}, {%0,%1,%2,%3};"
        : "+f"(c[0]),"+f"(c[1]),"+f"(c[2]),"+f"(c[3])
        : "r"(a[0]),"r"(a[1]),"r"(a[2]),"r"(a[3]), "r"(b[0]),"r"(b[1]));
}
// truncation split of two floats: h = packed bf16 hi (exact truncation),
// l = packed bf16 of exact residuals. a -> low half, b -> high half.
static __device__ __forceinline__ void split2(float a, float b, u32& h, u32& l){
    u32 ua = __float_as_uint(a), ub = __float_as_uint(b);
    h = __byte_perm(ua, ub, 0x7632);
    float la = a - __uint_as_float(ua & 0xFFFF0000u);
    float lb = b - __uint_as_float(ub & 0xFFFF0000u);
    asm("cvt.rn.bf16x2.f32 %0, %1, %2;" : "=r"(l) : "f"(lb), "f"(la));
}
static __device__ __forceinline__ void pack4(float4 x, u64& hv, u64& lv){
    u32 h01, l01, h23, l23;
    split2(x.x, x.y, h01, l01);
    split2(x.z, x.w, h23, l23);
    hv = (u64)h01 | ((u64)h23 << 32);
    lv = (u64)l01 | ((u64)l23 << 32);
}
static __device__ __forceinline__ float bf2f(u32 bits16){ return __uint_as_float(bits16 << 16); }

// non-trans gemm (A [m][k] rows, B [n][k] rows), 3 split products, warp 32x32 tile
static __device__ __forceinline__ void gemm_tile(float acc[2][4][4], u32 aH, u32 aL, u32 bH, u32 bL){
    #pragma unroll
    for (int ks = 0; ks < 8; ++ks){
        u32 ah[2][4], al[2][4], bh[2][4], bl[2][4];
        #pragma unroll
        for (int mi = 0; mi < 2; ++mi){
            LDSM_X4(ah[mi], aH + mi*(16*ST*2) + ks*32);
            LDSM_X4(al[mi], aL + mi*(16*ST*2) + ks*32);
        }
        #pragma unroll
        for (int nj = 0; nj < 2; ++nj){
            LDSM_X4(bh[nj], bH + nj*(16*ST*2) + ks*32);
            LDSM_X4(bl[nj], bL + nj*(16*ST*2) + ks*32);
        }
        #pragma unroll
        for (int mi = 0; mi < 2; ++mi)
        #pragma unroll
        for (int nj = 0; nj < 2; ++nj){
            mma16816(acc[mi][nj*2],   ah[mi], &bh[nj][0]);
            mma16816(acc[mi][nj*2+1], ah[mi], &bh[nj][2]);
        }
        #pragma unroll
        for (int mi = 0; mi < 2; ++mi)
        #pragma unroll
        for (int nj = 0; nj < 2; ++nj){
            mma16816(acc[mi][nj*2],   ah[mi], &bl[nj][0]);
            mma16816(acc[mi][nj*2+1], ah[mi], &bl[nj][2]);
        }
        #pragma unroll
        for (int mi = 0; mi < 2; ++mi)
        #pragma unroll
        for (int nj = 0; nj < 2; ++nj){
            mma16816(acc[mi][nj*2],   al[mi], &bh[nj][0]);
            mma16816(acc[mi][nj*2+1], al[mi], &bh[nj][2]);
        }
    }
}

// trans-B gemm (A [m][k] rows, B [k][n] rows via ldmatrix.trans)
static __device__ __forceinline__ void gemm_tile_tb(float acc[2][4][4], u32 aH, u32 aL, u32 bH, u32 bL){
    #pragma unroll
    for (int ks = 0; ks < 8; ++ks){
        u32 ah[2][4], al[2][4], bh[2][4], bl[2][4];
        #pragma unroll
        for (int mi = 0; mi < 2; ++mi){
            LDSM_X4(ah[mi], aH + mi*(16*ST*2) + ks*32);
            LDSM_X4(al[mi], aL + mi*(16*ST*2) + ks*32);
        }
        #pragma unroll
        for (int nj = 0; nj < 2; ++nj){
            LDSM_X4_T(bh[nj], bH + nj*32 + ks*(16*ST*2));
            LDSM_X4_T(bl[nj], bL + nj*32 + ks*(16*ST*2));
        }
        #pragma unroll
        for (int mi = 0; mi < 2; ++mi)
        #pragma unroll
        for (int nj = 0; nj < 2; ++nj){
            mma16816(acc[mi][nj*2],   ah[mi], &bh[nj][0]);
            mma16816(acc[mi][nj*2+1], ah[mi], &bh[nj][2]);
        }
        #pragma unroll
        for (int mi = 0; mi < 2; ++mi)
        #pragma unroll
        for (int nj = 0; nj < 2; ++nj){
            mma16816(acc[mi][nj*2],   ah[mi], &bl[nj][0]);
            mma16816(acc[mi][nj*2+1], ah[mi], &bl[nj][2]);
        }
        #pragma unroll
        for (int mi = 0; mi < 2; ++mi)
        #pragma unroll
        for (int nj = 0; nj < 2; ++nj){
            mma16816(acc[mi][nj*2],   al[mi], &bh[nj][0]);
            mma16816(acc[mi][nj*2+1], al[mi], &bh[nj][2]);
        }
    }
}

// -------- init --------
__global__ void kinit(){
    int t = blockIdx.x*blockDim.x + threadIdx.x;
    if (t < 24) g_znum[t] = 0;
    for (int i = t; i < 24*512; i += 16*256) g_zcnt[i] = 0;
}

// -------- scan Y slices 0..2 for exact zeros --------
__global__ void kscan(const float* __restrict__ Y){
    int gtid = blockIdx.x*blockDim.x + threadIdx.x;
    int bg   = gtid >> 16;
    int off4 = gtid & 65535;
    int b = bg / GG, g = bg % GG;
    const float4 y4 = reinterpret_cast<const float4*>(Y)[(size_t)(b*16 + g)*65536 + off4];
    int l = off4 * 4;
    int u = l >> 9, v = l & 511;
    float vals[4] = {y4.x, y4.y, y4.z, y4.w};
    #pragma unroll
    for (int r = 0; r < 4; ++r){
        if (vals[r] == 0.0f){
            int pos = atomicAdd(&g_znum[bg], 1);
            if (pos < ZCAP) g_zlist[bg*ZCAP + pos] = make_int2(u, v + r);
            atomicAdd(&g_zcnt[bg*512 + v + r], 1);
        }
    }
}

// -------- fused kernel: Gram -> T1/T2 -> Q -> output, one CTA per (b,f) --------
__global__ void __launch_bounds__(512, 1) kfuse(const float* __restrict__ infos,
                                                const float* __restrict__ Wd,
                                                const float* __restrict__ bd,
                                                const float* __restrict__ Wn,
                                                const float* __restrict__ bn,
                                                float* __restrict__ out){
    extern __shared__ __align__(16) char smc[];
    __shared__ float sT1[128], sT2[128], sVec[128], sBase[128];

    int bf = blockIdx.x, b = bf >> 4, f = bf & 15;
    int t = threadIdx.x, wid = t >> 5, lane = t & 31;
    int wm = wid & 3, wn = wid >> 2;
    int m0 = wm*32, n0 = wn*32;
    int g = lane >> 2, t4 = lane & 3;

    u32 sb = smem_u32(smc);
    u32 aBase = sb + (u32)(((m0 + (lane & 15))*ST + (lane >> 4)*8) * 2);
    u32 bBase = sb + (u32)(((n0 + (lane & 7) + ((lane >> 4) & 1)*8)*ST + ((lane >> 3) & 1)*8) * 2);
    u32 bToff = (u32)(((lane & 15)*ST + n0 + (lane >> 4)*8) * 2);

    if (t < 128){ sT1[t] = 0.0f; sT2[t] = 0.0f; }

    // ---- WS = W1+W3 fp32 [128][129] at S4 (untouched during Gram) ----
    {
        float* sWS = reinterpret_cast<float*>(smc + 4*TILEB);
        int d = t >> 2, ch = (t & 3)*32;
        #pragma unroll
        for (int i = 0; i < 8; ++i){
            int c0 = ch + i*4;
            float4 a  = *reinterpret_cast<const float4*>(Wd + d*384 + c0);
            float4 c3 = *reinterpret_cast<const float4*>(Wd + d*384 + 256 + c0);
            sWS[d*129 + c0 + 0] = a.x + c3.x;
            sWS[d*129 + c0 + 1] = a.y + c3.y;
            sWS[d*129 + c0 + 2] = a.z + c3.z;
            sWS[d*129 + c0 + 3] = a.w + c3.w;
        }
    }

    // ---- Gram: G = X X^T, K=512 in 4 chunks, reg-prefetched (X hi@S0, lo@S1) ----
    int cr = t >> 2, uh = (t & 3)*32;
    const float* xrow = infos + (((size_t)b*128 + cr)*16 + f)*512 + uh;
    float t2acc = 0.0f;
    float acc[2][4][4] = {};
    float4 pf[8];
    #pragma unroll
    for (int i = 0; i < 8; ++i) pf[i] = *reinterpret_cast<const float4*>(xrow + i*4);

    for (int kk = 0; kk < 4; ++kk){
        #pragma unroll
        for (int i = 0; i < 8; ++i){
            int ul = uh + i*4;
            t2acc += pf[i].x + pf[i].y + pf[i].z + pf[i].w;
            u64 hv, lv; pack4(pf[i], hv, lv);
            *reinterpret_cast<u64*>(smc + (cr*ST + ul)*2)         = hv;
            *reinterpret_cast<u64*>(smc + TILEB + (cr*ST + ul)*2) = lv;
        }
        __syncthreads();
        if (kk < 3){
            #pragma unroll
            for (int i = 0; i < 8; ++i) pf[i] = *reinterpret_cast<const float4*>(xrow + (kk+1)*128 + i*4);
        }
        gemm_tile(acc, aBase, aBase + TILEB, bBase, bBase + TILEB);
        __syncthreads();
    }
    // NOTE: pf now holds chunk 3 == output v-tile 3
    atomicAdd(&sT2[cr], t2acc);
    __syncthreads();

    // ---- T1 epilogue from Gram accumulators (WS @ S4) ----
    {
        const float* sWS = reinterpret_cast<const float*>(smc + 4*TILEB);
        #pragma unroll
        for (int mi = 0; mi < 2; ++mi){
            int r0 = m0 + mi*16 + g, r1 = r0 + 8;
            float s0 = 0.0f, s1 = 0.0f;
            #pragma unroll
            for (int ni = 0; ni < 4; ++ni){
                int col = n0 + ni*8 + 2*t4;
                s0 += acc[mi][ni][0]*sWS[r0*129 + col] + acc[mi][ni][1]*sWS[r0*129 + col + 1];
                s1 += acc[mi][ni][2]*sWS[r1*129 + col] + acc[mi][ni][3]*sWS[r1*129 + col + 1];
            }
            atomicAdd(&sT1[r0], s0);
            atomicAdd(&sT1[r1], s1);
        }
    }
    __syncthreads();
    if (t < 128){
        float t1v = sT1[t], t2v = sT2[t];
        g_T1[bf*128 + t] = t1v;
        g_T2[bf*128 + t] = t2v;
        sVec[t] = t1v + t2v * bd[t];
    }
    __syncthreads();

    // ---- Wn tiles (hi@S0, lo@S1) + BQ [c][e] rows (hi@S2, lo@S3) ----
    {
        int o = t >> 2, ch = (t & 3)*32;
        #pragma unroll
        for (int i = 0; i < 8; ++i){
            int c0 = ch + i*4;
            float4 w = *reinterpret_cast<const float4*>(Wn + o*128 + c0);
            u64 hv, lv; pack4(w, hv, lv);
            *reinterpret_cast<u64*>(smc + (o*ST + c0)*2)         = hv;
            *reinterpret_cast<u64*>(smc + TILEB + (o*ST + c0)*2) = lv;
        }
    }
    {
        int c = t >> 2, eb = (t & 3)*32;
        float t2c = sT2[c];
        #pragma unroll
        for (int i = 0; i < 8; ++i){
            int e0 = eb + i*4;
            float4 a  = *reinterpret_cast<const float4*>(Wd + c*384 + 128 + e0);
            float4 c3 = *reinterpret_cast<const float4*>(Wd + c*384 + 256 + e0);
            float4 v4 = make_float4(t2c*(a.x - c3.x), t2c*(a.y - c3.y), t2c*(a.z - c3.z), t2c*(a.w - c3.w));
            u64 hv, lv; pack4(v4, hv, lv);
            *reinterpret_cast<u64*>(smc + 2*TILEB + (c*ST + e0)*2) = hv;
            *reinterpret_cast<u64*>(smc + 3*TILEB + (c*ST + e0)*2) = lv;
        }
    }
    __syncthreads();

    // ---- k0[o] (t<128, from Wn smem) then Q gemm (all warps) ----
    float ksum = 0.0f;
    if (t < 128){
        #pragma unroll 4
        for (int c2 = 0; c2 < 128; c2 += 2){
            u32 hw = *reinterpret_cast<const u32*>(smc + (t*ST + c2)*2);
            u32 lw = *reinterpret_cast<const u32*>(smc + TILEB + (t*ST + c2)*2);
            float w0 = bf2f(hw & 0xffff) + bf2f(lw & 0xffff);
            float w1 = bf2f(hw >> 16)    + bf2f(lw >> 16);
            ksum += w0*sVec[c2] + w1*sVec[c2 + 1];
        }
    }
    float qacc[2][4][4] = {};
    gemm_tile_tb(qacc, aBase, aBase + TILEB, sb + 2*TILEB + bToff, sb + 3*TILEB + bToff);
    __syncthreads();

    // ---- Q epilogue: split to bf16 hi/lo straight into S0/S1 (overwrite Wn) ----
    #pragma unroll
    for (int mi = 0; mi < 2; ++mi){
        int r0 = m0 + mi*16 + g, r1 = r0 + 8;
        #pragma unroll
        for (int ni = 0; ni < 4; ++ni){
            int col = n0 + ni*8 + 2*t4;
            u32 h01, l01;
            split2(qacc[mi][ni][0], qacc[mi][ni][1], h01, l01);
            *reinterpret_cast<u32*>(smc + (r0*ST + col)*2)         = h01;
            *reinterpret_cast<u32*>(smc + TILEB + (r0*ST + col)*2) = l01;
            split2(qacc[mi][ni][2], qacc[mi][ni][3], h01, l01);
            *reinterpret_cast<u32*>(smc + (r1*ST + col)*2)         = h01;
            *reinterpret_cast<u32*>(smc + TILEB + (r1*ST + col)*2) = l01;
        }
    }
    if (t < 128) sBase[t] = ksum*(1.0f/512.0f) + bn[t];

    // ---- fill buf0 (S2/S3) with v-tile 3 (pf already holds it); prefetch vt0 ----
    {
        #pragma unroll
        for (int i = 0; i < 8; ++i){
            int vl = uh + i*4;
            u64 hv, lv; pack4(pf[i], hv, lv);
            *reinterpret_cast<u64*>(smc + 2*TILEB + (cr*ST + vl)*2) = hv;
            *reinterpret_cast<u64*>(smc + 3*TILEB + (cr*ST + vl)*2) = lv;
        }
        #pragma unroll
        for (int i = 0; i < 8; ++i) pf[i] = *reinterpret_cast<const float4*>(xrow + i*4);   // vt0
    }
    __syncthreads();

    // ---- output loop, tile order {3,0,1,2}, double-buffered S2/S3 <-> S4/S5 ----
    const float inv = 1.0f/512.0f;
    #pragma unroll
    for (int it = 0; it < 4; ++it){
        const int ord[4] = {3,0,1,2};
        int vt = ord[it];
        u32 curB = sb + (2 + 2*(it & 1))*TILEB + bToff;
        u32 othW = (2 + 2*((it + 1) & 1))*TILEB;
        if (it < 3){
            #pragma unroll
            for (int i = 0; i < 8; ++i){
                int vl = uh + i*4;
                u64 hv, lv; pack4(pf[i], hv, lv);
                *reinterpret_cast<u64*>(smc + othW + (cr*ST + vl)*2)         = hv;
                *reinterpret_cast<u64*>(smc + othW + TILEB + (cr*ST + vl)*2) = lv;
            }
            if (it < 2){
                #pragma unroll
                for (int i = 0; i < 8; ++i) pf[i] = *reinterpret_cast<const float4*>(xrow + ord[it+2]*128 + i*4);
            }
        }

        float acc2[2][4][4] = {};
        gemm_tile_tb(acc2, aBase, aBase + TILEB, curB, curB + TILEB);

        int v0 = vt*128;
        #pragma unroll
        for (int mi = 0; mi < 2; ++mi){
            int o0 = m0 + mi*16 + g, o1 = o0 + 8;
            size_t base0 = ((size_t)(b*128 + o0)*16 + f)*512 + v0;
            size_t base1 = ((size_t)(b*128 + o1)*16 + f)*512 + v0;
            #pragma unroll
            for (int ni = 0; ni < 4; ++ni){
                int vc = n0 + ni*8 + 2*t4;
                float2 r0v, r1v;
                r0v.x = fmaxf(fmaf(acc2[mi][ni][0], inv, sBase[o0]), 0.0f);
                r0v.y = fmaxf(fmaf(acc2[mi][ni][1], inv, sBase[o0]), 0.0f);
                r1v.x = fmaxf(fmaf(acc2[mi][ni][2], inv, sBase[o1]), 0.0f);
                r1v.y = fmaxf(fmaf(acc2[mi][ni][3], inv, sBase[o1]), 0.0f);
                *reinterpret_cast<float2*>(out + base0 + vc) = r0v;
                *reinterpret_cast<float2*>(out + base1 + vc) = r1v;
            }
        }
        __syncthreads();
    }
}

// -------- K4: exact recompute of zero-affected output columns (smem-staged) --------
__global__ void __launch_bounds__(256, 1) k4_fix(const float* __restrict__ infos,
                                                 const float* __restrict__ Wd,
                                                 const float* __restrict__ bd,
                                                 const float* __restrict__ Wn,
                                                 const float* __restrict__ bn,
                                                 float* __restrict__ out){
    int bf = blockIdx.x;
    int b = bf >> 4, f = bf & 15;
    int g = (f == 0) ? 0 : ((f <= 11) ? 1 : 2);
    int bg = b*GG + g;
    int nz = g_znum[bg]; if (nz > ZCAP) nz = ZCAP;
    if (nz == 0) return;

    int t = threadIdx.x;   // 256
    extern __shared__ float sw[];
    float* sWS  = sw;               // (W1+W3)[c][e], padded 129
    float* sWD2 = sw + 128*129;     // (W2-W3)[c][e]
    float* sWN  = sw + 2*128*129;   // Wn[o][c]

    __shared__ float sXv[128], sAgg[128];
    __shared__ float sXu[16][128];
    __shared__ int   sUs[16];
    __shared__ int   sM;

    // cooperative coalesced staging of the three 128x128 matrices
    {
        int c = t >> 1, h = (t & 1)*64;
        #pragma unroll
        for (int i = 0; i < 16; ++i){
            int e = h + i*4;
            float4 w1 = *reinterpret_cast<const float4*>(Wd + c*384 + e);
            float4 w2 = *reinterpret_cast<const float4*>(Wd + c*384 + 128 + e);
            float4 w3 = *reinterpret_cast<const float4*>(Wd + c*384 + 256 + e);
            float4 wn = *reinterpret_cast<const float4*>(Wn + c*128 + e);
            sWS[c*129 + e + 0] = w1.x + w3.x;  sWD2[c*129 + e + 0] = w2.x - w3.x;
            sWS[c*129 + e + 1] = w1.y + w3.y;  sWD2[c*129 + e + 1] = w2.y - w3.y;
            sWS[c*129 + e + 2] = w1.z + w3.z;  sWD2[c*129 + e + 2] = w2.z - w3.z;
            sWS[c*129 + e + 3] = w1.w + w3.w;  sWD2[c*129 + e + 3] = w2.w - w3.w;
            sWN[c*129 + e + 0] = wn.x;
            sWN[c*129 + e + 1] = wn.y;
            sWN[c*129 + e + 2] = wn.z;
            sWN[c*129 + e + 3] = wn.w;
        }
    }
    __syncthreads();

    for (int i = 0; i < nz; ++i){
        int vz = g_zlist[bg*ZCAP + i].y;
        bool dup = false;
        for (int jj = 0; jj < i; ++jj)
            if (g_zlist[bg*ZCAP + jj].y == vz){ dup = true; break; }
        if (dup) continue;

        if (t == 0){
            int m = 0;
            for (int jj = i; jj < nz; ++jj){
                int2 e2 = g_zlist[bg*ZCAP + jj];
                if (e2.y == vz && m < 16) sUs[m++] = e2.x;
            }
            sM = m;
        }
        __syncthreads();
        int m = sM;

        if (t < 128){
            sXv[t] = infos[(size_t)(b*2048 + t*16 + f)*512 + vz];
            for (int k = 0; k < m; ++k)
                sXu[k][t] = infos[(size_t)(b*2048 + t*16 + f)*512 + sUs[k]];
        }
        __syncthreads();

        if (t < 128){
            int c = t;
            float Dv = 0.0f;
            #pragma unroll 8
            for (int e = 0; e < 128; ++e) Dv += sXv[e] * sWD2[c*129 + e];
            float a1 = g_T1[bf*128 + c];
            float a2 = g_T2[bf*128 + c];
            for (int k = 0; k < m; ++k){
                float S = 0.0f;
                #pragma unroll 8
                for (int e = 0; e < 128; ++e) S += sXu[k][e] * sWS[c*129 + e];
                a1 -= sXu[k][c] * S;
                a2 -= sXu[k][c];
            }
            int degi = 512 - g_zcnt[bg*512 + vz];
            float deg = (float)(degi > 1 ? degi : 1);
            sAgg[c] = (a1 + a2*(Dv + bd[c])) / deg;
        }
        __syncthreads();

        if (t < 128){
            float s = 0.0f;
            #pragma unroll 8
            for (int cc = 0; cc < 128; ++cc) s += sAgg[cc] * sWN[t*129 + cc];
            s += bn[t];
            out[(size_t)(b*2048 + t*16 + f)*512 + vz] = fmaxf(s, 0.0f);
        }
        __syncthreads();
    }
}

extern "C" void kernel_launch(void* const* d_in, const int* in_sizes, int n_in,
                              void* d_out, int out_size){
    const float* Y     = (const float*)d_in[0];
    const float* infos = (const float*)d_in[1];
    const float* Wd    = (const float*)d_in[2];
    const float* bd    = (const float*)d_in[3];
    const float* Wn    = (const float*)d_in[4];
    const float* bn    = (const float*)d_in[5];
    float* out = (float*)d_out;

    cudaFuncSetAttribute(kfuse,  cudaFuncAttributeMaxDynamicSharedMemorySize, DYNSM);
    cudaFuncSetAttribute(k4_fix, cudaFuncAttributeMaxDynamicSharedMemorySize, K4SMEM);

    kinit<<<16, 256>>>();
    kscan<<<6144, 256>>>(Y);
    kfuse<<<128, 512, DYNSM>>>(infos, Wd, bd, Wn, bn, out);
    k4_fix<<<128, 256, K4SMEM>>>(infos, Wd, bd, Wn, bn, out);
}

// round 11
// speedup vs baseline: 1.4554x; 1.4554x over previous
#include <cuda_runtime.h>
#include <cuda_bf16.h>
#include <cstdint>

typedef unsigned int u32;
typedef unsigned long long u64;
typedef unsigned short u16;

#define GG 3
#define ZCAP 4096
#define ST 136                 // bf16 elements per padded tile row (272 B)
#define TILEB (128*ST*2)       // 34816 bytes per 128x128 bf16 tile
#define DYNSM (6*TILEB)        // 208896
#define K4SMEM (3*128*129*4)   // 198144

// ---------------- device scratch (allocation-free) ----------------
__device__ float g_T1[16384];
__device__ float g_T2[16384];
__device__ int   g_znum[24];
__device__ int   g_zcnt[24*512];
__device__ int2  g_zlist[24*ZCAP];

// ---------------- helpers ----------------
static __device__ __forceinline__ u32 smem_u32(const void* p){
    u32 a;
    asm("{ .reg .u64 t; cvta.to.shared.u64 t, %1; cvt.u32.u64 %0, t; }" : "=r"(a) : "l"(p));
    return a;
}
#define LDSM_X4(r, a) \
    asm volatile("ldmatrix.sync.aligned.m8n8.x4.shared.b16 {%0,%1,%2,%3}, [%4];" \
        : "=r"((r)[0]),"=r"((r)[1]),"=r"((r)[2]),"=r"((r)[3]) : "r"(a))
#define LDSM_X4_T(r, a) \
    asm volatile("ldmatrix.sync.aligned.m8n8.x4.trans.shared.b16 {%0,%1,%2,%3}, [%4];" \
        : "=r"((r)[0]),"=r"((r)[1]),"=r"((r)[2]),"=r"((r)[3]) : "r"(a))

static __device__ __forceinline__ void mma16816(float* c, const u32* a, const u32* b){
    asm volatile("mma.sync.aligned.m16n8k16.row.col.f32.bf16.bf16.f32 "
        "{%0,%1,%2,%3}, {%4,%5,%6,%7}, {%8,%9}, {%0,%1,%2,%3};"
        : "+f"(c[0]),"+f"(c[1]),"+f"(c[2]),"+f"(c[3])
        : "r"(a[0]),"r"(a[1]),"r"(a[2]),"r"(a[3]), "r"(b[0]),"r"(b[1]));
}
// truncation split of two floats: h = packed bf16 hi (exact truncation),
// l = packed bf16 of exact residuals. a -> low half, b -> high half.
static __device__ __forceinline__ void split2(float a, float b, u32& h, u32& l){
    u32 ua = __float_as_uint(a), ub = __float_as_uint(b);
    h = __byte_perm(ua, ub, 0x7632);
    float la = a - __uint_as_float(ua & 0xFFFF0000u);
    float lb = b - __uint_as_float(ub & 0xFFFF0000u);
    asm("cvt.rn.bf16x2.f32 %0, %1, %2;" : "=r"(l) : "f"(lb), "f"(la));
}
static __device__ __forceinline__ void pack4(float4 x, u64& hv, u64& lv){
    u32 h01, l01, h23, l23;
    split2(x.x, x.y, h01, l01);
    split2(x.z, x.w, h23, l23);
    hv = (u64)h01 | ((u64)h23 << 32);
    lv = (u64)l01 | ((u64)l23 << 32);
}
static __device__ __forceinline__ float bf2f(u32 bits16){ return __uint_as_float(bits16 << 16); }

// non-trans gemm (A [m][k] rows, B [n][k] rows), 3 split products, warp 32x32 tile
static __device__ __forceinline__ void gemm_tile(float acc[2][4][4], u32 aH, u32 aL, u32 bH, u32 bL){
    #pragma unroll
    for (int ks = 0; ks < 8; ++ks){
        u32 ah[2][4], al[2][4], bh[2][4], bl[2][4];
        #pragma unroll
        for (int mi = 0; mi < 2; ++mi){
            LDSM_X4(ah[mi], aH + mi*(16*ST*2) + ks*32);
            LDSM_X4(al[mi], aL + mi*(16*ST*2) + ks*32);
        }
        #pragma unroll
        for (int nj = 0; nj < 2; ++nj){
            LDSM_X4(bh[nj], bH + nj*(16*ST*2) + ks*32);
            LDSM_X4(bl[nj], bL + nj*(16*ST*2) + ks*32);
        }
        #pragma unroll
        for (int mi = 0; mi < 2; ++mi)
        #pragma unroll
        for (int nj = 0; nj < 2; ++nj){
            mma16816(acc[mi][nj*2],   ah[mi], &bh[nj][0]);
            mma16816(acc[mi][nj*2+1], ah[mi], &bh[nj][2]);
        }
        #pragma unroll
        for (int mi = 0; mi < 2; ++mi)
        #pragma unroll
        for (int nj = 0; nj < 2; ++nj){
            mma16816(acc[mi][nj*2],   ah[mi], &bl[nj][0]);
            mma16816(acc[mi][nj*2+1], ah[mi], &bl[nj][2]);
        }
        #pragma unroll
        for (int mi = 0; mi < 2; ++mi)
        #pragma unroll
        for (int nj = 0; nj < 2; ++nj){
            mma16816(acc[mi][nj*2],   al[mi], &bh[nj][0]);
            mma16816(acc[mi][nj*2+1], al[mi], &bh[nj][2]);
        }
    }
}

// trans-B gemm (A [m][k] rows, B [k][n] rows via ldmatrix.trans)
static __device__ __forceinline__ void gemm_tile_tb(float acc[2][4][4], u32 aH, u32 aL, u32 bH, u32 bL){
    #pragma unroll
    for (int ks = 0; ks < 8; ++ks){
        u32 ah[2][4], al[2][4], bh[2][4], bl[2][4];
        #pragma unroll
        for (int mi = 0; mi < 2; ++mi){
            LDSM_X4(ah[mi], aH + mi*(16*ST*2) + ks*32);
            LDSM_X4(al[mi], aL + mi*(16*ST*2) + ks*32);
        }
        #pragma unroll
        for (int nj = 0; nj < 2; ++nj){
            LDSM_X4_T(bh[nj], bH + nj*32 + ks*(16*ST*2));
            LDSM_X4_T(bl[nj], bL + nj*32 + ks*(16*ST*2));
        }
        #pragma unroll
        for (int mi = 0; mi < 2; ++mi)
        #pragma unroll
        for (int nj = 0; nj < 2; ++nj){
            mma16816(acc[mi][nj*2],   ah[mi], &bh[nj][0]);
            mma16816(acc[mi][nj*2+1], ah[mi], &bh[nj][2]);
        }
        #pragma unroll
        for (int mi = 0; mi < 2; ++mi)
        #pragma unroll
        for (int nj = 0; nj < 2; ++nj){
            mma16816(acc[mi][nj*2],   ah[mi], &bl[nj][0]);
            mma16816(acc[mi][nj*2+1], ah[mi], &bl[nj][2]);
        }
        #pragma unroll
        for (int mi = 0; mi < 2; ++mi)
        #pragma unroll
        for (int nj = 0; nj < 2; ++nj){
            mma16816(acc[mi][nj*2],   al[mi], &bh[nj][0]);
            mma16816(acc[mi][nj*2+1], al[mi], &bh[nj][2]);
        }
    }
}

// -------- init --------
__global__ void kinit(){
    int t = blockIdx.x*blockDim.x + threadIdx.x;
    if (t < 24) g_znum[t] = 0;
    for (int i = t; i < 24*512; i += 16*256) g_zcnt[i] = 0;
}

// -------- scan Y slices 0..2 for exact zeros --------
__global__ void kscan(const float* __restrict__ Y){
    int gtid = blockIdx.x*blockDim.x + threadIdx.x;
    int bg   = gtid >> 16;
    int off4 = gtid & 65535;
    int b = bg / GG, g = bg % GG;
    const float4 y4 = reinterpret_cast<const float4*>(Y)[(size_t)(b*16 + g)*65536 + off4];
    int l = off4 * 4;
    int u = l >> 9, v = l & 511;
    float vals[4] = {y4.x, y4.y, y4.z, y4.w};
    #pragma unroll
    for (int r = 0; r < 4; ++r){
        if (vals[r] == 0.0f){
            int pos = atomicAdd(&g_znum[bg], 1);
            if (pos < ZCAP) g_zlist[bg*ZCAP + pos] = make_int2(u, v + r);
            atomicAdd(&g_zcnt[bg*512 + v + r], 1);
        }
    }
}

// -------- fused kernel: Gram -> T1/T2 -> Q -> output, one CTA per (b,f) --------
__global__ void __launch_bounds__(512, 1) kfuse(const float* __restrict__ infos,
                                                const float* __restrict__ Wd,
                                                const float* __restrict__ bd,
                                                const float* __restrict__ Wn,
                                                const float* __restrict__ bn,
                                                float* __restrict__ out){
    extern __shared__ __align__(16) char smc[];
    __shared__ float sT1[128], sT2[128], sVec[128], sBase[128];

    int bf = blockIdx.x, b = bf >> 4, f = bf & 15;
    int t = threadIdx.x, wid = t >> 5, lane = t & 31;
    int wm = wid & 3, wn = wid >> 2;
    int m0 = wm*32, n0 = wn*32;
    int g = lane >> 2, t4 = lane & 3;

    u32 sb = smem_u32(smc);
    u32 aBase = sb + (u32)(((m0 + (lane & 15))*ST + (lane >> 4)*8) * 2);
    u32 bBase = sb + (u32)(((n0 + (lane & 7) + ((lane >> 4) & 1)*8)*ST + ((lane >> 3) & 1)*8) * 2);
    u32 bToff = (u32)(((lane & 15)*ST + n0 + (lane >> 4)*8) * 2);

    if (t < 128){ sT1[t] = 0.0f; sT2[t] = 0.0f; }

    // ---- WS = W1+W3 fp32 [128][129] at S4 (untouched during Gram) ----
    {
        float* sWS = reinterpret_cast<float*>(smc + 4*TILEB);
        int d = t >> 2, ch = (t & 3)*32;
        #pragma unroll
        for (int i = 0; i < 8; ++i){
            int c0 = ch + i*4;
            float4 a  = *reinterpret_cast<const float4*>(Wd + d*384 + c0);
            float4 c3 = *reinterpret_cast<const float4*>(Wd + d*384 + 256 + c0);
            sWS[d*129 + c0 + 0] = a.x + c3.x;
            sWS[d*129 + c0 + 1] = a.y + c3.y;
            sWS[d*129 + c0 + 2] = a.z + c3.z;
            sWS[d*129 + c0 + 3] = a.w + c3.w;
        }
    }

    // ---- Gram: G = X X^T, K=512 in 4 chunks, reg-prefetched (X hi@S0, lo@S1) ----
    int cr = t >> 2, uh = (t & 3)*32;
    const float* xrow = infos + (((size_t)b*128 + cr)*16 + f)*512 + uh;
    float t2acc = 0.0f;
    float acc[2][4][4] = {};
    float4 pf[8];
    #pragma unroll
    for (int i = 0; i < 8; ++i) pf[i] = *reinterpret_cast<const float4*>(xrow + i*4);

    for (int kk = 0; kk < 4; ++kk){
        #pragma unroll
        for (int i = 0; i < 8; ++i){
            int ul = uh + i*4;
            t2acc += pf[i].x + pf[i].y + pf[i].z + pf[i].w;
            u64 hv, lv; pack4(pf[i], hv, lv);
            *reinterpret_cast<u64*>(smc + (cr*ST + ul)*2)         = hv;
            *reinterpret_cast<u64*>(smc + TILEB + (cr*ST + ul)*2) = lv;
        }
        __syncthreads();
        if (kk < 3){
            #pragma unroll
            for (int i = 0; i < 8; ++i) pf[i] = *reinterpret_cast<const float4*>(xrow + (kk+1)*128 + i*4);
        }
        gemm_tile(acc, aBase, aBase + TILEB, bBase, bBase + TILEB);
        __syncthreads();
    }
    // NOTE: pf now holds chunk 3 == output v-tile 3
    atomicAdd(&sT2[cr], t2acc);
    __syncthreads();

    // ---- T1 epilogue from Gram accumulators (WS @ S4) ----
    {
        const float* sWS = reinterpret_cast<const float*>(smc + 4*TILEB);
        #pragma unroll
        for (int mi = 0; mi < 2; ++mi){
            int r0 = m0 + mi*16 + g, r1 = r0 + 8;
            float s0 = 0.0f, s1 = 0.0f;
            #pragma unroll
            for (int ni = 0; ni < 4; ++ni){
                int col = n0 + ni*8 + 2*t4;
                s0 += acc[mi][ni][0]*sWS[r0*129 + col] + acc[mi][ni][1]*sWS[r0*129 + col + 1];
                s1 += acc[mi][ni][2]*sWS[r1*129 + col] + acc[mi][ni][3]*sWS[r1*129 + col + 1];
            }
            atomicAdd(&sT1[r0], s0);
            atomicAdd(&sT1[r1], s1);
        }
    }
    __syncthreads();
    if (t < 128){
        float t1v = sT1[t], t2v = sT2[t];
        g_T1[bf*128 + t] = t1v;
        g_T2[bf*128 + t] = t2v;
        sVec[t] = t1v + t2v * bd[t];
    }
    __syncthreads();

    // ---- Wn tiles (hi@S0, lo@S1) + BQ [c][e] rows (hi@S2, lo@S3) ----
    {
        int o = t >> 2, ch = (t & 3)*32;
        #pragma unroll
        for (int i = 0; i < 8; ++i){
            int c0 = ch + i*4;
            float4 w = *reinterpret_cast<const float4*>(Wn + o*128 + c0);
            u64 hv, lv; pack4(w, hv, lv);
            *reinterpret_cast<u64*>(smc + (o*ST + c0)*2)         = hv;
            *reinterpret_cast<u64*>(smc + TILEB + (o*ST + c0)*2) = lv;
        }
    }
    {
        int c = t >> 2, eb = (t & 3)*32;
        float t2c = sT2[c];
        #pragma unroll
        for (int i = 0; i < 8; ++i){
            int e0 = eb + i*4;
            float4 a  = *reinterpret_cast<const float4*>(Wd + c*384 + 128 + e0);
            float4 c3 = *reinterpret_cast<const float4*>(Wd + c*384 + 256 + e0);
            float4 v4 = make_float4(t2c*(a.x - c3.x), t2c*(a.y - c3.y), t2c*(a.z - c3.z), t2c*(a.w - c3.w));
            u64 hv, lv; pack4(v4, hv, lv);
            *reinterpret_cast<u64*>(smc + 2*TILEB + (c*ST + e0)*2) = hv;
            *reinterpret_cast<u64*>(smc + 3*TILEB + (c*ST + e0)*2) = lv;
        }
    }
    __syncthreads();

    // ---- k0[o] (t<128, from Wn smem) then Q gemm (all warps) ----
    float ksum = 0.0f;
    if (t < 128){
        #pragma unroll 4
        for (int c2 = 0; c2 < 128; c2 += 2){
            u32 hw = *reinterpret_cast<const u32*>(smc + (t*ST + c2)*2);
            u32 lw = *reinterpret_cast<const u32*>(smc + TILEB + (t*ST + c2)*2);
            float w0 = bf2f(hw & 0xffff) + bf2f(lw & 0xffff);
            float w1 = bf2f(hw >> 16)    + bf2f(lw >> 16);
            ksum += w0*sVec[c2] + w1*sVec[c2 + 1];
        }
    }
    float qacc[2][4][4] = {};
    gemm_tile_tb(qacc, aBase, aBase + TILEB, sb + 2*TILEB + bToff, sb + 3*TILEB + bToff);
    __syncthreads();

    // ---- Q epilogue: split to bf16 hi/lo straight into S0/S1 (overwrite Wn) ----
    #pragma unroll
    for (int mi = 0; mi < 2; ++mi){
        int r0 = m0 + mi*16 + g, r1 = r0 + 8;
        #pragma unroll
        for (int ni = 0; ni < 4; ++ni){
            int col = n0 + ni*8 + 2*t4;
            u32 h01, l01;
            split2(qacc[mi][ni][0], qacc[mi][ni][1], h01, l01);
            *reinterpret_cast<u32*>(smc + (r0*ST + col)*2)         = h01;
            *reinterpret_cast<u32*>(smc + TILEB + (r0*ST + col)*2) = l01;
            split2(qacc[mi][ni][2], qacc[mi][ni][3], h01, l01);
            *reinterpret_cast<u32*>(smc + (r1*ST + col)*2)         = h01;
            *reinterpret_cast<u32*>(smc + TILEB + (r1*ST + col)*2) = l01;
        }
    }
    if (t < 128) sBase[t] = ksum*(1.0f/512.0f) + bn[t];

    // ---- fill buf0 (S2/S3) with v-tile 3 (pf already holds it); prefetch vt0 ----
    {
        #pragma unroll
        for (int i = 0; i < 8; ++i){
            int vl = uh + i*4;
            u64 hv, lv; pack4(pf[i], hv, lv);
            *reinterpret_cast<u64*>(smc + 2*TILEB + (cr*ST + vl)*2) = hv;
            *reinterpret_cast<u64*>(smc + 3*TILEB + (cr*ST + vl)*2) = lv;
        }
        #pragma unroll
        for (int i = 0; i < 8; ++i) pf[i] = *reinterpret_cast<const float4*>(xrow + i*4);   // vt0
    }
    __syncthreads();

    // ---- output loop, tile order {3,0,1,2}, double-buffered S2/S3 <-> S4/S5 ----
    const float inv = 1.0f/512.0f;
    #pragma unroll
    for (int it = 0; it < 4; ++it){
        const int ord[4] = {3,0,1,2};
        int vt = ord[it];
        u32 curB = sb + (2 + 2*(it & 1))*TILEB + bToff;
        u32 othW = (2 + 2*((it + 1) & 1))*TILEB;
        if (it < 3){
            #pragma unroll
            for (int i = 0; i < 8; ++i){
                int vl = uh + i*4;
                u64 hv, lv; pack4(pf[i], hv, lv);
                *reinterpret_cast<u64*>(smc + othW + (cr*ST + vl)*2)         = hv;
                *reinterpret_cast<u64*>(smc + othW + TILEB + (cr*ST + vl)*2) = lv;
            }
            if (it < 2){
                #pragma unroll
                for (int i = 0; i < 8; ++i) pf[i] = *reinterpret_cast<const float4*>(xrow + ord[it+2]*128 + i*4);
            }
        }

        float acc2[2][4][4] = {};
        gemm_tile_tb(acc2, aBase, aBase + TILEB, curB, curB + TILEB);

        int v0 = vt*128;
        #pragma unroll
        for (int mi = 0; mi < 2; ++mi){
            int o0 = m0 + mi*16 + g, o1 = o0 + 8;
            size_t base0 = ((size_t)(b*128 + o0)*16 + f)*512 + v0;
            size_t base1 = ((size_t)(b*128 + o1)*16 + f)*512 + v0;
            #pragma unroll
            for (int ni = 0; ni < 4; ++ni){
                int vc = n0 + ni*8 + 2*t4;
                float2 r0v, r1v;
                r0v.x = fmaxf(fmaf(acc2[mi][ni][0], inv, sBase[o0]), 0.0f);
                r0v.y = fmaxf(fmaf(acc2[mi][ni][1], inv, sBase[o0]), 0.0f);
                r1v.x = fmaxf(fmaf(acc2[mi][ni][2], inv, sBase[o1]), 0.0f);
                r1v.y = fmaxf(fmaf(acc2[mi][ni][3], inv, sBase[o1]), 0.0f);
                *reinterpret_cast<float2*>(out + base0 + vc) = r0v;
                *reinterpret_cast<float2*>(out + base1 + vc) = r1v;
            }
        }
        __syncthreads();
    }
}

// -------- K4: exact recompute of zero-affected output columns --------
// grid (16 slots, 128 bf), 256 threads; slot-parallel over zeros; smem-staged weights.
__global__ void __launch_bounds__(256, 1) k4_fix(const float* __restrict__ infos,
                                                 const float* __restrict__ Wd,
                                                 const float* __restrict__ bd,
                                                 const float* __restrict__ Wn,
                                                 const float* __restrict__ bn,
                                                 float* __restrict__ out){
    int slot = blockIdx.x;          // 0..15
    int bf   = blockIdx.y;
    int b = bf >> 4, f = bf & 15;
    int g = (f == 0) ? 0 : ((f <= 11) ? 1 : 2);
    int bg = b*GG + g;
    int nz = g_znum[bg]; if (nz > ZCAP) nz = ZCAP;
    if (slot >= nz) return;         // covers nz==0 too

    int t = threadIdx.x;            // 256
    extern __shared__ float sw[];
    float* sWS  = sw;               // (W1+W3)[c][e], padded 129
    float* sWD2 = sw + 128*129;     // (W2-W3)[c][e]
    float* sWN  = sw + 2*128*129;   // Wn[o][c]

    __shared__ float sXv[128], sAgg[128];
    __shared__ float sXu[16][128];
    __shared__ int   sUs[16];
    __shared__ int   sM;

    // cooperative staging, bounded unroll (keeps in-flight loads ~8 float4)
    {
        int c = t >> 1, h = (t & 1)*64;
        #pragma unroll 2
        for (int i = 0; i < 16; ++i){
            int e = h + i*4;
            float4 w1 = *reinterpret_cast<const float4*>(Wd + c*384 + e);
            float4 w2 = *reinterpret_cast<const float4*>(Wd + c*384 + 128 + e);
            float4 w3 = *reinterpret_cast<const float4*>(Wd + c*384 + 256 + e);
            float4 wnv = *reinterpret_cast<const float4*>(Wn + c*128 + e);
            sWS[c*129 + e + 0] = w1.x + w3.x;  sWD2[c*129 + e + 0] = w2.x - w3.x;
            sWS[c*129 + e + 1] = w1.y + w3.y;  sWD2[c*129 + e + 1] = w2.y - w3.y;
            sWS[c*129 + e + 2] = w1.z + w3.z;  sWD2[c*129 + e + 2] = w2.z - w3.z;
            sWS[c*129 + e + 3] = w1.w + w3.w;  sWD2[c*129 + e + 3] = w2.w - w3.w;
            sWN[c*129 + e + 0] = wnv.x;
            sWN[c*129 + e + 1] = wnv.y;
            sWN[c*129 + e + 2] = wnv.z;
            sWN[c*129 + e + 3] = wnv.w;
        }
    }
    __syncthreads();

    for (int i = slot; i < nz; i += 16){
        int vz = g_zlist[bg*ZCAP + i].y;
        bool dup = false;
        for (int jj = 0; jj < i; ++jj)
            if (g_zlist[bg*ZCAP + jj].y == vz){ dup = true; break; }
        if (dup) continue;

        if (t == 0){
            int m = 0;
            for (int jj = i; jj < nz; ++jj){
                int2 e2 = g_zlist[bg*ZCAP + jj];
                if (e2.y == vz && m < 16) sUs[m++] = e2.x;
            }
            sM = m;
        }
        __syncthreads();
        int m = sM;

        if (t < 128){
            sXv[t] = infos[(size_t)(b*2048 + t*16 + f)*512 + vz];
            for (int k = 0; k < m; ++k)
                sXu[k][t] = infos[(size_t)(b*2048 + t*16 + f)*512 + sUs[k]];
        }
        __syncthreads();

        if (t < 128){
            int c = t;
            float Dv = 0.0f;
            #pragma unroll 8
            for (int e = 0; e < 128; ++e) Dv += sXv[e] * sWD2[c*129 + e];
            float a1 = g_T1[bf*128 + c];
            float a2 = g_T2[bf*128 + c];
            for (int k = 0; k < m; ++k){
                float S = 0.0f;
                #pragma unroll 8
                for (int e = 0; e < 128; ++e) S += sXu[k][e] * sWS[c*129 + e];
                a1 -= sXu[k][c] * S;
                a2 -= sXu[k][c];
            }
            int degi = 512 - g_zcnt[bg*512 + vz];
            float deg = (float)(degi > 1 ? degi : 1);
            sAgg[c] = (a1 + a2*(Dv + bd[c])) / deg;
        }
        __syncthreads();

        if (t < 128){
            float s = 0.0f;
            #pragma unroll 8
            for (int cc = 0; cc < 128; ++cc) s += sAgg[cc] * sWN[t*129 + cc];
            s += bn[t];
            out[(size_t)(b*2048 + t*16 + f)*512 + vz] = fmaxf(s, 0.0f);
        }
        __syncthreads();
    }
}

extern "C" void kernel_launch(void* const* d_in, const int* in_sizes, int n_in,
                              void* d_out, int out_size){
    const float* Y     = (const float*)d_in[0];
    const float* infos = (const float*)d_in[1];
    const float* Wd    = (const float*)d_in[2];
    const float* bd    = (const float*)d_in[3];
    const float* Wn    = (const float*)d_in[4];
    const float* bn    = (const float*)d_in[5];
    float* out = (float*)d_out;

    cudaFuncSetAttribute(kfuse,  cudaFuncAttributeMaxDynamicSharedMemorySize, DYNSM);
    cudaFuncSetAttribute(k4_fix, cudaFuncAttributeMaxDynamicSharedMemorySize, K4SMEM);

    kinit<<<16, 256>>>();
    kscan<<<6144, 256>>>(Y);
    kfuse<<<128, 512, DYNSM>>>(infos, Wd, bd, Wn, bn, out);
    k4_fix<<<dim3(16, 128), 256, K4SMEM>>>(infos, Wd, bd, Wn, bn, out);
}

// round 12
// speedup vs baseline: 1.5299x; 1.0512x over previous
#include <cuda_runtime.h>
#include <cuda_bf16.h>
#include <cstdint>

typedef unsigned int u32;
typedef unsigned long long u64;
typedef unsigned short u16;

#define GG 3
#define ZCAP 4096
#define ST 136                 // bf16 elements per padded tile row (272 B)
#define TILEB (128*ST*2)       // 34816 bytes per 128x128 bf16 tile
#define DYNSM (6*TILEB)        // 208896
#define K4SMEM (3*128*129*4)   // 198144

// ---------------- device scratch (allocation-free) ----------------
__device__ float g_T1[16384];
__device__ float g_T2[16384];
__device__ int   g_znum[24];
__device__ int   g_zcnt[24*512];
__device__ int2  g_zlist[24*ZCAP];

// ---------------- helpers ----------------
static __device__ __forceinline__ u32 smem_u32(const void* p){
    u32 a;
    asm("{ .reg .u64 t; cvta.to.shared.u64 t, %1; cvt.u32.u64 %0, t; }" : "=r"(a) : "l"(p));
    return a;
}
#define LDSM_X4(r, a) \
    asm volatile("ldmatrix.sync.aligned.m8n8.x4.shared.b16 {%0,%1,%2,%3}, [%4];" \
        : "=r"((r)[0]),"=r"((r)[1]),"=r"((r)[2]),"=r"((r)[3]) : "r"(a))
#define LDSM_X4_T(r, a) \
    asm volatile("ldmatrix.sync.aligned.m8n8.x4.trans.shared.b16 {%0,%1,%2,%3}, [%4];" \
        : "=r"((r)[0]),"=r"((r)[1]),"=r"((r)[2]),"=r"((r)[3]) : "r"(a))

static __device__ __forceinline__ void mma16816(float* c, const u32* a, const u32* b){
    asm volatile("mma.sync.aligned.m16n8k16.row.col.f32.bf16.bf16.f32 "
        "{%0,%1,%2,%3}, {%4,%5,%6,%7}, {%8,%9}, {%0,%1,%2,%3};"
        : "+f"(c[0]),"+f"(c[1]),"+f"(c[2]),"+f"(c[3])
        : "r"(a[0]),"r"(a[1]),"r"(a[2]),"r"(a[3]), "r"(b[0]),"r"(b[1]));
}
// truncation split of two floats: h = packed bf16 hi (exact truncation),
// l = packed bf16 of exact residuals. a -> low half, b -> high half.
static __device__ __forceinline__ void split2(float a, float b, u32& h, u32& l){
    u32 ua = __float_as_uint(a), ub = __float_as_uint(b);
    h = __byte_perm(ua, ub, 0x7632);
    float la = a - __uint_as_float(ua & 0xFFFF0000u);
    float lb = b - __uint_as_float(ub & 0xFFFF0000u);
    asm("cvt.rn.bf16x2.f32 %0, %1, %2;" : "=r"(l) : "f"(lb), "f"(la));
}
static __device__ __forceinline__ void pack4(float4 x, u64& hv, u64& lv){
    u32 h01, l01, h23, l23;
    split2(x.x, x.y, h01, l01);
    split2(x.z, x.w, h23, l23);
    hv = (u64)h01 | ((u64)h23 << 32);
    lv = (u64)l01 | ((u64)l23 << 32);
}
static __device__ __forceinline__ float bf2f(u32 bits16){ return __uint_as_float(bits16 << 16); }

// fill one X chunk (hi/lo split) into a tile buffer; returns partial T2 sum
static __device__ __forceinline__ float fill_x(char* smc, u32 bufOff, const float* src,
                                               int cr, int uh){
    float t2 = 0.0f;
    #pragma unroll
    for (int i = 0; i < 8; ++i){
        int ul = uh + i*4;
        float4 x = *reinterpret_cast<const float4*>(src + i*4);
        t2 += x.x + x.y + x.z + x.w;
        u64 hv, lv; pack4(x, hv, lv);
        *reinterpret_cast<u64*>(smc + bufOff + (cr*ST + ul)*2)         = hv;
        *reinterpret_cast<u64*>(smc + bufOff + TILEB + (cr*ST + ul)*2) = lv;
    }
    return t2;
}

// non-trans gemm (A [m][k] rows, B [n][k] rows), 3 split products, warp 32x32 tile
static __device__ __forceinline__ void gemm_tile(float acc[2][4][4], u32 aH, u32 aL, u32 bH, u32 bL){
    #pragma unroll
    for (int ks = 0; ks < 8; ++ks){
        u32 ah[2][4], al[2][4], bh[2][4], bl[2][4];
        #pragma unroll
        for (int mi = 0; mi < 2; ++mi){
            LDSM_X4(ah[mi], aH + mi*(16*ST*2) + ks*32);
            LDSM_X4(al[mi], aL + mi*(16*ST*2) + ks*32);
        }
        #pragma unroll
        for (int nj = 0; nj < 2; ++nj){
            LDSM_X4(bh[nj], bH + nj*(16*ST*2) + ks*32);
            LDSM_X4(bl[nj], bL + nj*(16*ST*2) + ks*32);
        }
        #pragma unroll
        for (int mi = 0; mi < 2; ++mi)
        #pragma unroll
        for (int nj = 0; nj < 2; ++nj){
            mma16816(acc[mi][nj*2],   ah[mi], &bh[nj][0]);
            mma16816(acc[mi][nj*2+1], ah[mi], &bh[nj][2]);
        }
        #pragma unroll
        for (int mi = 0; mi < 2; ++mi)
        #pragma unroll
        for (int nj = 0; nj < 2; ++nj){
            mma16816(acc[mi][nj*2],   ah[mi], &bl[nj][0]);
            mma16816(acc[mi][nj*2+1], ah[mi], &bl[nj][2]);
        }
        #pragma unroll
        for (int mi = 0; mi < 2; ++mi)
        #pragma unroll
        for (int nj = 0; nj < 2; ++nj){
            mma16816(acc[mi][nj*2],   al[mi], &bh[nj][0]);
            mma16816(acc[mi][nj*2+1], al[mi], &bh[nj][2]);
        }
    }
}

// trans-B gemm (A [m][k] rows, B [k][n] rows via ldmatrix.trans)
static __device__ __forceinline__ void gemm_tile_tb(float acc[2][4][4], u32 aH, u32 aL, u32 bH, u32 bL){
    #pragma unroll
    for (int ks = 0; ks < 8; ++ks){
        u32 ah[2][4], al[2][4], bh[2][4], bl[2][4];
        #pragma unroll
        for (int mi = 0; mi < 2; ++mi){
            LDSM_X4(ah[mi], aH + mi*(16*ST*2) + ks*32);
            LDSM_X4(al[mi], aL + mi*(16*ST*2) + ks*32);
        }
        #pragma unroll
        for (int nj = 0; nj < 2; ++nj){
            LDSM_X4_T(bh[nj], bH + nj*32 + ks*(16*ST*2));
            LDSM_X4_T(bl[nj], bL + nj*32 + ks*(16*ST*2));
        }
        #pragma unroll
        for (int mi = 0; mi < 2; ++mi)
        #pragma unroll
        for (int nj = 0; nj < 2; ++nj){
            mma16816(acc[mi][nj*2],   ah[mi], &bh[nj][0]);
            mma16816(acc[mi][nj*2+1], ah[mi], &bh[nj][2]);
        }
        #pragma unroll
        for (int mi = 0; mi < 2; ++mi)
        #pragma unroll
        for (int nj = 0; nj < 2; ++nj){
            mma16816(acc[mi][nj*2],   ah[mi], &bl[nj][0]);
            mma16816(acc[mi][nj*2+1], ah[mi], &bl[nj][2]);
        }
        #pragma unroll
        for (int mi = 0; mi < 2; ++mi)
        #pragma unroll
        for (int nj = 0; nj < 2; ++nj){
            mma16816(acc[mi][nj*2],   al[mi], &bh[nj][0]);
            mma16816(acc[mi][nj*2+1], al[mi], &bh[nj][2]);
        }
    }
}

// -------- init --------
__global__ void kinit(){
    int t = blockIdx.x*blockDim.x + threadIdx.x;
    if (t < 24) g_znum[t] = 0;
    for (int i = t; i < 24*512; i += 16*256) g_zcnt[i] = 0;
}

// -------- scan Y slices 0..2 for exact zeros --------
__global__ void kscan(const float* __restrict__ Y){
    int gtid = blockIdx.x*blockDim.x + threadIdx.x;
    int bg   = gtid >> 16;
    int off4 = gtid & 65535;
    int b = bg / GG, g = bg % GG;
    const float4 y4 = reinterpret_cast<const float4*>(Y)[(size_t)(b*16 + g)*65536 + off4];
    int l = off4 * 4;
    int u = l >> 9, v = l & 511;
    float vals[4] = {y4.x, y4.y, y4.z, y4.w};
    #pragma unroll
    for (int r = 0; r < 4; ++r){
        if (vals[r] == 0.0f){
            int pos = atomicAdd(&g_znum[bg], 1);
            if (pos < ZCAP) g_zlist[bg*ZCAP + pos] = make_int2(u, v + r);
            atomicAdd(&g_zcnt[bg*512 + v + r], 1);
        }
    }
}

// -------- fused kernel: Gram -> T1/T2 -> Q -> output, one CTA per (b,f) --------
__global__ void __launch_bounds__(512, 1) kfuse(const float* __restrict__ infos,
                                                const float* __restrict__ Wd,
                                                const float* __restrict__ bd,
                                                const float* __restrict__ Wn,
                                                const float* __restrict__ bn,
                                                float* __restrict__ out){
    extern __shared__ __align__(16) char smc[];
    __shared__ float sT1[128], sT2[128], sVec[128], sBase[128];

    int bf = blockIdx.x, b = bf >> 4, f = bf & 15;
    int t = threadIdx.x, wid = t >> 5, lane = t & 31;
    int wm = wid & 3, wn = wid >> 2;
    int m0 = wm*32, n0 = wn*32;
    int g = lane >> 2, t4 = lane & 3;

    u32 sb = smem_u32(smc);
    u32 aBase = sb + (u32)(((m0 + (lane & 15))*ST + (lane >> 4)*8) * 2);
    u32 bBase = sb + (u32)(((n0 + (lane & 7) + ((lane >> 4) & 1)*8)*ST + ((lane >> 3) & 1)*8) * 2);
    u32 bToff = (u32)(((lane & 15)*ST + n0 + (lane >> 4)*8) * 2);

    if (t < 128){ sT1[t] = 0.0f; sT2[t] = 0.0f; }

    // ---- WS = W1+W3 fp32 [128][129] at S4 (untouched during Gram) ----
    {
        float* sWS = reinterpret_cast<float*>(smc + 4*TILEB);
        int d = t >> 2, ch = (t & 3)*32;
        #pragma unroll
        for (int i = 0; i < 8; ++i){
            int c0 = ch + i*4;
            float4 a  = *reinterpret_cast<const float4*>(Wd + d*384 + c0);
            float4 c3 = *reinterpret_cast<const float4*>(Wd + d*384 + 256 + c0);
            sWS[d*129 + c0 + 0] = a.x + c3.x;
            sWS[d*129 + c0 + 1] = a.y + c3.y;
            sWS[d*129 + c0 + 2] = a.z + c3.z;
            sWS[d*129 + c0 + 3] = a.w + c3.w;
        }
    }

    // ---- Gram: G = X X^T, K=512 in 4 chunks, double-buffered S0/S1 <-> S2/S3 ----
    int cr = t >> 2, uh = (t & 3)*32;
    const float* xrow = infos + (((size_t)b*128 + cr)*16 + f)*512 + uh;
    float t2acc = 0.0f;
    float acc[2][4][4] = {};

    t2acc += fill_x(smc, 0, xrow, cr, uh);              // chunk 0 -> buf0 (S0/S1)
    __syncthreads();
    #pragma unroll
    for (int kk = 0; kk < 4; ++kk){
        if (kk < 3)
            t2acc += fill_x(smc, ((kk + 1) & 1) ? 2u*TILEB : 0u,
                            xrow + (kk + 1)*128, cr, uh);
        u32 off = (kk & 1) ? 2u*TILEB : 0u;
        gemm_tile(acc, aBase + off, aBase + off + TILEB, bBase + off, bBase + off + TILEB);
        __syncthreads();
    }
    // NOTE: S2/S3 now holds chunk 3 == output v-tile 3 (preserved below)
    atomicAdd(&sT2[cr], t2acc);
    __syncthreads();

    // ---- T1 epilogue from Gram accumulators (WS @ S4) ----
    {
        const float* sWS = reinterpret_cast<const float*>(smc + 4*TILEB);
        #pragma unroll
        for (int mi = 0; mi < 2; ++mi){
            int r0 = m0 + mi*16 + g, r1 = r0 + 8;
            float s0 = 0.0f, s1 = 0.0f;
            #pragma unroll
            for (int ni = 0; ni < 4; ++ni){
                int col = n0 + ni*8 + 2*t4;
                s0 += acc[mi][ni][0]*sWS[r0*129 + col] + acc[mi][ni][1]*sWS[r0*129 + col + 1];
                s1 += acc[mi][ni][2]*sWS[r1*129 + col] + acc[mi][ni][3]*sWS[r1*129 + col + 1];
            }
            atomicAdd(&sT1[r0], s0);
            atomicAdd(&sT1[r1], s1);
        }
    }
    __syncthreads();
    if (t < 128){
        float t1v = sT1[t], t2v = sT2[t];
        g_T1[bf*128 + t] = t1v;
        g_T2[bf*128 + t] = t2v;
        sVec[t] = t1v + t2v * bd[t];
    }
    __syncthreads();

    // ---- Wn tiles (hi@S0, lo@S1) + BQ [c][e] rows (hi@S4, lo@S5; WS dead) ----
    {
        int o = t >> 2, ch = (t & 3)*32;
        #pragma unroll
        for (int i = 0; i < 8; ++i){
            int c0 = ch + i*4;
            float4 w = *reinterpret_cast<const float4*>(Wn + o*128 + c0);
            u64 hv, lv; pack4(w, hv, lv);
            *reinterpret_cast<u64*>(smc + (o*ST + c0)*2)         = hv;
            *reinterpret_cast<u64*>(smc + TILEB + (o*ST + c0)*2) = lv;
        }
    }
    {
        int c = t >> 2, eb = (t & 3)*32;
        float t2c = sT2[c];
        #pragma unroll
        for (int i = 0; i < 8; ++i){
            int e0 = eb + i*4;
            float4 a  = *reinterpret_cast<const float4*>(Wd + c*384 + 128 + e0);
            float4 c3 = *reinterpret_cast<const float4*>(Wd + c*384 + 256 + e0);
            float4 v4 = make_float4(t2c*(a.x - c3.x), t2c*(a.y - c3.y), t2c*(a.z - c3.z), t2c*(a.w - c3.w));
            u64 hv, lv; pack4(v4, hv, lv);
            *reinterpret_cast<u64*>(smc + 4*TILEB + (c*ST + e0)*2) = hv;
            *reinterpret_cast<u64*>(smc + 5*TILEB + (c*ST + e0)*2) = lv;
        }
    }
    __syncthreads();

    // ---- k0[o] (t<128, from Wn smem) then Q gemm (all warps) ----
    float ksum = 0.0f;
    if (t < 128){
        #pragma unroll 4
        for (int c2 = 0; c2 < 128; c2 += 2){
            u32 hw = *reinterpret_cast<const u32*>(smc + (t*ST + c2)*2);
            u32 lw = *reinterpret_cast<const u32*>(smc + TILEB + (t*ST + c2)*2);
            float w0 = bf2f(hw & 0xffff) + bf2f(lw & 0xffff);
            float w1 = bf2f(hw >> 16)    + bf2f(lw >> 16);
            ksum += w0*sVec[c2] + w1*sVec[c2 + 1];
        }
    }
    float qacc[2][4][4] = {};
    gemm_tile_tb(qacc, aBase, aBase + TILEB, sb + 4*TILEB + bToff, sb + 5*TILEB + bToff);
    __syncthreads();

    // ---- Q epilogue: split to bf16 hi/lo straight into S0/S1 (overwrite Wn) ----
    #pragma unroll
    for (int mi = 0; mi < 2; ++mi){
        int r0 = m0 + mi*16 + g, r1 = r0 + 8;
        #pragma unroll
        for (int ni = 0; ni < 4; ++ni){
            int col = n0 + ni*8 + 2*t4;
            u32 h01, l01;
            split2(qacc[mi][ni][0], qacc[mi][ni][1], h01, l01);
            *reinterpret_cast<u32*>(smc + (r0*ST + col)*2)         = h01;
            *reinterpret_cast<u32*>(smc + TILEB + (r0*ST + col)*2) = l01;
            split2(qacc[mi][ni][2], qacc[mi][ni][3], h01, l01);
            *reinterpret_cast<u32*>(smc + (r1*ST + col)*2)         = h01;
            *reinterpret_cast<u32*>(smc + TILEB + (r1*ST + col)*2) = l01;
        }
    }
    if (t < 128) sBase[t] = ksum*(1.0f/512.0f) + bn[t];

    // prefetch vt0 for the output loop (S2/S3 already holds vt3)
    float4 pf[8];
    #pragma unroll
    for (int i = 0; i < 8; ++i) pf[i] = *reinterpret_cast<const float4*>(xrow + i*4);
    __syncthreads();

    // ---- output loop, tile order {3,0,1,2}, double-buffered S2/S3 <-> S4/S5 ----
    const float inv = 1.0f/512.0f;
    #pragma unroll
    for (int it = 0; it < 4; ++it){
        const int ord[4] = {3,0,1,2};
        int vt = ord[it];
        u32 curB = sb + (2 + 2*(it & 1))*TILEB + bToff;
        u32 othW = (2 + 2*((it + 1) & 1))*TILEB;
        if (it < 3){
            #pragma unroll
            for (int i = 0; i < 8; ++i){
                int vl = uh + i*4;
                u64 hv, lv; pack4(pf[i], hv, lv);
                *reinterpret_cast<u64*>(smc + othW + (cr*ST + vl)*2)         = hv;
                *reinterpret_cast<u64*>(smc + othW + TILEB + (cr*ST + vl)*2) = lv;
            }
            if (it < 2){
                #pragma unroll
                for (int i = 0; i < 8; ++i) pf[i] = *reinterpret_cast<const float4*>(xrow + ord[it+2]*128 + i*4);
            }
        }

        float acc2[2][4][4] = {};
        gemm_tile_tb(acc2, aBase, aBase + TILEB, curB, curB + TILEB);

        int v0 = vt*128;
        #pragma unroll
        for (int mi = 0; mi < 2; ++mi){
            int o0 = m0 + mi*16 + g, o1 = o0 + 8;
            size_t base0 = ((size_t)(b*128 + o0)*16 + f)*512 + v0;
            size_t base1 = ((size_t)(b*128 + o1)*16 + f)*512 + v0;
            #pragma unroll
            for (int ni = 0; ni < 4; ++ni){
                int vc = n0 + ni*8 + 2*t4;
                float2 r0v, r1v;
                r0v.x = fmaxf(fmaf(acc2[mi][ni][0], inv, sBase[o0]), 0.0f);
                r0v.y = fmaxf(fmaf(acc2[mi][ni][1], inv, sBase[o0]), 0.0f);
                r1v.x = fmaxf(fmaf(acc2[mi][ni][2], inv, sBase[o1]), 0.0f);
                r1v.y = fmaxf(fmaf(acc2[mi][ni][3], inv, sBase[o1]), 0.0f);
                *reinterpret_cast<float2*>(out + base0 + vc) = r0v;
                *reinterpret_cast<float2*>(out + base1 + vc) = r1v;
            }
        }
        __syncthreads();
    }
}

// -------- K4: exact recompute of zero-affected output columns --------
// grid (2 slots, 128 bf): small grid avoids smem-allocation wave serialization.
__global__ void __launch_bounds__(256, 1) k4_fix(const float* __restrict__ infos,
                                                 const float* __restrict__ Wd,
                                                 const float* __restrict__ bd,
                                                 const float* __restrict__ Wn,
                                                 const float* __restrict__ bn,
                                                 float* __restrict__ out){
    int slot = blockIdx.x;          // 0..1
    int bf   = blockIdx.y;
    int b = bf >> 4, f = bf & 15;
    int g = (f == 0) ? 0 : ((f <= 11) ? 1 : 2);
    int bg = b*GG + g;
    int nz = g_znum[bg]; if (nz > ZCAP) nz = ZCAP;
    if (slot >= nz) return;

    int t = threadIdx.x;            // 256
    extern __shared__ float sw[];
    float* sWS  = sw;               // (W1+W3)[c][e], padded 129
    float* sWD2 = sw + 128*129;     // (W2-W3)[c][e]
    float* sWN  = sw + 2*128*129;   // Wn[o][c]

    __shared__ float sXv[128], sAgg[128];
    __shared__ float sXu[16][128];
    __shared__ int   sUs[16];
    __shared__ int   sM;

    // cooperative staging, bounded unroll
    {
        int c = t >> 1, h = (t & 1)*64;
        #pragma unroll 2
        for (int i = 0; i < 16; ++i){
            int e = h + i*4;
            float4 w1 = *reinterpret_cast<const float4*>(Wd + c*384 + e);
            float4 w2 = *reinterpret_cast<const float4*>(Wd + c*384 + 128 + e);
            float4 w3 = *reinterpret_cast<const float4*>(Wd + c*384 + 256 + e);
            float4 wnv = *reinterpret_cast<const float4*>(Wn + c*128 + e);
            sWS[c*129 + e + 0] = w1.x + w3.x;  sWD2[c*129 + e + 0] = w2.x - w3.x;
            sWS[c*129 + e + 1] = w1.y + w3.y;  sWD2[c*129 + e + 1] = w2.y - w3.y;
            sWS[c*129 + e + 2] = w1.z + w3.z;  sWD2[c*129 + e + 2] = w2.z - w3.z;
            sWS[c*129 + e + 3] = w1.w + w3.w;  sWD2[c*129 + e + 3] = w2.w - w3.w;
            sWN[c*129 + e + 0] = wnv.x;
            sWN[c*129 + e + 1] = wnv.y;
            sWN[c*129 + e + 2] = wnv.z;
            sWN[c*129 + e + 3] = wnv.w;
        }
    }
    __syncthreads();

    for (int i = slot; i < nz; i += 2){
        int vz = g_zlist[bg*ZCAP + i].y;
        bool dup = false;
        for (int jj = 0; jj < i; ++jj)
            if (g_zlist[bg*ZCAP + jj].y == vz){ dup = true; break; }
        if (dup) continue;

        if (t == 0){
            int m = 0;
            for (int jj = i; jj < nz; ++jj){
                int2 e2 = g_zlist[bg*ZCAP + jj];
                if (e2.y == vz && m < 16) sUs[m++] = e2.x;
            }
            sM = m;
        }
        __syncthreads();
        int m = sM;

        if (t < 128){
            sXv[t] = infos[(size_t)(b*2048 + t*16 + f)*512 + vz];
            for (int k = 0; k < m; ++k)
                sXu[k][t] = infos[(size_t)(b*2048 + t*16 + f)*512 + sUs[k]];
        }
        __syncthreads();

        if (t < 128){
            int c = t;
            float Dv = 0.0f;
            #pragma unroll 8
            for (int e = 0; e < 128; ++e) Dv += sXv[e] * sWD2[c*129 + e];
            float a1 = g_T1[bf*128 + c];
            float a2 = g_T2[bf*128 + c];
            for (int k = 0; k < m; ++k){
                float S = 0.0f;
                #pragma unroll 8
                for (int e = 0; e < 128; ++e) S += sXu[k][e] * sWS[c*129 + e];
                a1 -= sXu[k][c] * S;
                a2 -= sXu[k][c];
            }
            int degi = 512 - g_zcnt[bg*512 + vz];
            float deg = (float)(degi > 1 ? degi : 1);
            sAgg[c] = (a1 + a2*(Dv + bd[c])) / deg;
        }
        __syncthreads();

        if (t < 128){
            float s = 0.0f;
            #pragma unroll 8
            for (int cc = 0; cc < 128; ++cc) s += sAgg[cc] * sWN[t*129 + cc];
            s += bn[t];
            out[(size_t)(b*2048 + t*16 + f)*512 + vz] = fmaxf(s, 0.0f);
        }
        __syncthreads();
    }
}

extern "C" void kernel_launch(void* const* d_in, const int* in_sizes, int n_in,
                              void* d_out, int out_size){
    const float* Y     = (const float*)d_in[0];
    const float* infos = (const float*)d_in[1];
    const float* Wd    = (const float*)d_in[2];
    const float* bd    = (const float*)d_in[3];
    const float* Wn    = (const float*)d_in[4];
    const float* bn    = (const float*)d_in[5];
    float* out = (float*)d_out;

    cudaFuncSetAttribute(kfuse,  cudaFuncAttributeMaxDynamicSharedMemorySize, DYNSM);
    cudaFuncSetAttribute(k4_fix, cudaFuncAttributeMaxDynamicSharedMemorySize, K4SMEM);

    kinit<<<16, 256>>>();
    kscan<<<6144, 256>>>(Y);
    kfuse<<<128, 512, DYNSM>>>(infos, Wd, bd, Wn, bn, out);
    k4_fix<<<dim3(2, 128), 256, K4SMEM>>>(infos, Wd, bd, Wn, bn, out);
}

// round 13
// speedup vs baseline: 1.5854x; 1.0363x over previous
#include <cuda_runtime.h>
#include <cuda_bf16.h>
#include <cstdint>

typedef unsigned int u32;
typedef unsigned long long u64;
typedef unsigned short u16;

#define GG 3
#define ZCAP 4096
#define ST 136                 // bf16 elements per padded tile row (272 B)
#define TILEB (128*ST*2)       // 34816 bytes per 128x128 bf16 tile
#define DYNSM (6*TILEB)        // 208896

// ---------------- device scratch (allocation-free) ----------------
__device__ float g_T1[16384];
__device__ float g_T2[16384];
__device__ int   g_znum[24];
__device__ int   g_zcnt[24*512];
__device__ int2  g_zlist[24*ZCAP];

// ---------------- helpers ----------------
static __device__ __forceinline__ u32 smem_u32(const void* p){
    u32 a;
    asm("{ .reg .u64 t; cvta.to.shared.u64 t, %1; cvt.u32.u64 %0, t; }" : "=r"(a) : "l"(p));
    return a;
}
#define LDSM_X4(r, a) \
    asm volatile("ldmatrix.sync.aligned.m8n8.x4.shared.b16 {%0,%1,%2,%3}, [%4];" \
        : "=r"((r)[0]),"=r"((r)[1]),"=r"((r)[2]),"=r"((r)[3]) : "r"(a))
#define LDSM_X4_T(r, a) \
    asm volatile("ldmatrix.sync.aligned.m8n8.x4.trans.shared.b16 {%0,%1,%2,%3}, [%4];" \
        : "=r"((r)[0]),"=r"((r)[1]),"=r"((r)[2]),"=r"((r)[3]) : "r"(a))

static __device__ __forceinline__ void mma16816(float* c, const u32* a, const u32* b){
    asm volatile("mma.sync.aligned.m16n8k16.row.col.f32.bf16.bf16.f32 "
        "{%0,%1,%2,%3}, {%4,%5,%6,%7}, {%8,%9}, {%0,%1,%2,%3};"
        : "+f"(c[0]),"+f"(c[1]),"+f"(c[2]),"+f"(c[3])
        : "r"(a[0]),"r"(a[1]),"r"(a[2]),"r"(a[3]), "r"(b[0]),"r"(b[1]));
}
// truncation split of two floats: h = packed bf16 hi (exact truncation),
// l = packed bf16 of exact residuals. a -> low half, b -> high half.
static __device__ __forceinline__ void split2(float a, float b, u32& h, u32& l){
    u32 ua = __float_as_uint(a), ub = __float_as_uint(b);
    h = __byte_perm(ua, ub, 0x7632);
    float la = a - __uint_as_float(ua & 0xFFFF0000u);
    float lb = b - __uint_as_float(ub & 0xFFFF0000u);
    asm("cvt.rn.bf16x2.f32 %0, %1, %2;" : "=r"(l) : "f"(lb), "f"(la));
}
static __device__ __forceinline__ void pack4(float4 x, u64& hv, u64& lv){
    u32 h01, l01, h23, l23;
    split2(x.x, x.y, h01, l01);
    split2(x.z, x.w, h23, l23);
    hv = (u64)h01 | ((u64)h23 << 32);
    lv = (u64)l01 | ((u64)l23 << 32);
}
static __device__ __forceinline__ float bf2f(u32 bits16){ return __uint_as_float(bits16 << 16); }

static __device__ __forceinline__ float warp_sum(float v){
    #pragma unroll
    for (int off = 16; off; off >>= 1) v += __shfl_xor_sync(0xFFFFFFFFu, v, off);
    return v;
}

// fill one X chunk (hi/lo split) into a tile buffer; returns partial T2 sum
static __device__ __forceinline__ float fill_x(char* smc, u32 bufOff, const float* src,
                                               int cr, int uh){
    float t2 = 0.0f;
    #pragma unroll
    for (int i = 0; i < 8; ++i){
        int ul = uh + i*4;
        float4 x = *reinterpret_cast<const float4*>(src + i*4);
        t2 += x.x + x.y + x.z + x.w;
        u64 hv, lv; pack4(x, hv, lv);
        *reinterpret_cast<u64*>(smc + bufOff + (cr*ST + ul)*2)         = hv;
        *reinterpret_cast<u64*>(smc + bufOff + TILEB + (cr*ST + ul)*2) = lv;
    }
    return t2;
}

// non-trans gemm (A [m][k] rows, B [n][k] rows), 3 split products, warp 32x32 tile
static __device__ __forceinline__ void gemm_tile(float acc[2][4][4], u32 aH, u32 aL, u32 bH, u32 bL){
    #pragma unroll
    for (int ks = 0; ks < 8; ++ks){
        u32 ah[2][4], al[2][4], bh[2][4], bl[2][4];
        #pragma unroll
        for (int mi = 0; mi < 2; ++mi){
            LDSM_X4(ah[mi], aH + mi*(16*ST*2) + ks*32);
            LDSM_X4(al[mi], aL + mi*(16*ST*2) + ks*32);
        }
        #pragma unroll
        for (int nj = 0; nj < 2; ++nj){
            LDSM_X4(bh[nj], bH + nj*(16*ST*2) + ks*32);
            LDSM_X4(bl[nj], bL + nj*(16*ST*2) + ks*32);
        }
        #pragma unroll
        for (int mi = 0; mi < 2; ++mi)
        #pragma unroll
        for (int nj = 0; nj < 2; ++nj){
            mma16816(acc[mi][nj*2],   ah[mi], &bh[nj][0]);
            mma16816(acc[mi][nj*2+1], ah[mi], &bh[nj][2]);
        }
        #pragma unroll
        for (int mi = 0; mi < 2; ++mi)
        #pragma unroll
        for (int nj = 0; nj < 2; ++nj){
            mma16816(acc[mi][nj*2],   ah[mi], &bl[nj][0]);
            mma16816(acc[mi][nj*2+1], ah[mi], &bl[nj][2]);
        }
        #pragma unroll
        for (int mi = 0; mi < 2; ++mi)
        #pragma unroll
        for (int nj = 0; nj < 2; ++nj){
            mma16816(acc[mi][nj*2],   al[mi], &bh[nj][0]);
            mma16816(acc[mi][nj*2+1], al[mi], &bh[nj][2]);
        }
    }
}

// trans-B gemm (A [m][k] rows, B [k][n] rows via ldmatrix.trans)
static __device__ __forceinline__ void gemm_tile_tb(float acc[2][4][4], u32 aH, u32 aL, u32 bH, u32 bL){
    #pragma unroll
    for (int ks = 0; ks < 8; ++ks){
        u32 ah[2][4], al[2][4], bh[2][4], bl[2][4];
        #pragma unroll
        for (int mi = 0; mi < 2; ++mi){
            LDSM_X4(ah[mi], aH + mi*(16*ST*2) + ks*32);
            LDSM_X4(al[mi], aL + mi*(16*ST*2) + ks*32);
        }
        #pragma unroll
        for (int nj = 0; nj < 2; ++nj){
            LDSM_X4_T(bh[nj], bH + nj*32 + ks*(16*ST*2));
            LDSM_X4_T(bl[nj], bL + nj*32 + ks*(16*ST*2));
        }
        #pragma unroll
        for (int mi = 0; mi < 2; ++mi)
        #pragma unroll
        for (int nj = 0; nj < 2; ++nj){
            mma16816(acc[mi][nj*2],   ah[mi], &bh[nj][0]);
            mma16816(acc[mi][nj*2+1], ah[mi], &bh[nj][2]);
        }
        #pragma unroll
        for (int mi = 0; mi < 2; ++mi)
        #pragma unroll
        for (int nj = 0; nj < 2; ++nj){
            mma16816(acc[mi][nj*2],   ah[mi], &bl[nj][0]);
            mma16816(acc[mi][nj*2+1], ah[mi], &bl[nj][2]);
        }
        #pragma unroll
        for (int mi = 0; mi < 2; ++mi)
        #pragma unroll
        for (int nj = 0; nj < 2; ++nj){
            mma16816(acc[mi][nj*2],   al[mi], &bh[nj][0]);
            mma16816(acc[mi][nj*2+1], al[mi], &bh[nj][2]);
        }
    }
}

// -------- init --------
__global__ void kinit(){
    int t = blockIdx.x*blockDim.x + threadIdx.x;
    if (t < 24) g_znum[t] = 0;
    for (int i = t; i < 24*512; i += 16*256) g_zcnt[i] = 0;
}

// -------- scan Y slices 0..2 for exact zeros --------
__global__ void kscan(const float* __restrict__ Y){
    int gtid = blockIdx.x*blockDim.x + threadIdx.x;
    int bg   = gtid >> 16;
    int off4 = gtid & 65535;
    int b = bg / GG, g = bg % GG;
    const float4 y4 = reinterpret_cast<const float4*>(Y)[(size_t)(b*16 + g)*65536 + off4];
    int l = off4 * 4;
    int u = l >> 9, v = l & 511;
    float vals[4] = {y4.x, y4.y, y4.z, y4.w};
    #pragma unroll
    for (int r = 0; r < 4; ++r){
        if (vals[r] == 0.0f){
            int pos = atomicAdd(&g_znum[bg], 1);
            if (pos < ZCAP) g_zlist[bg*ZCAP + pos] = make_int2(u, v + r);
            atomicAdd(&g_zcnt[bg*512 + v + r], 1);
        }
    }
}

// -------- fused kernel: Gram -> T1/T2 -> Q -> output, one CTA per (b,f) --------
__global__ void __launch_bounds__(512, 1) kfuse(const float* __restrict__ infos,
                                                const float* __restrict__ Wd,
                                                const float* __restrict__ bd,
                                                const float* __restrict__ Wn,
                                                const float* __restrict__ bn,
                                                float* __restrict__ out){
    extern __shared__ __align__(16) char smc[];
    __shared__ float sT1[128], sT2[128], sVec[128], sBase[128];

    int bf = blockIdx.x, b = bf >> 4, f = bf & 15;
    int t = threadIdx.x, wid = t >> 5, lane = t & 31;
    int wm = wid & 3, wn = wid >> 2;
    int m0 = wm*32, n0 = wn*32;
    int g = lane >> 2, t4 = lane & 3;

    u32 sb = smem_u32(smc);
    u32 aBase = sb + (u32)(((m0 + (lane & 15))*ST + (lane >> 4)*8) * 2);
    u32 bBase = sb + (u32)(((n0 + (lane & 7) + ((lane >> 4) & 1)*8)*ST + ((lane >> 3) & 1)*8) * 2);
    u32 bToff = (u32)(((lane & 15)*ST + n0 + (lane >> 4)*8) * 2);

    if (t < 128){ sT1[t] = 0.0f; sT2[t] = 0.0f; }

    // ---- WS = W1+W3 fp32 [128][129] at S4 (untouched during Gram) ----
    {
        float* sWS = reinterpret_cast<float*>(smc + 4*TILEB);
        int d = t >> 2, ch = (t & 3)*32;
        #pragma unroll
        for (int i = 0; i < 8; ++i){
            int c0 = ch + i*4;
            float4 a  = *reinterpret_cast<const float4*>(Wd + d*384 + c0);
            float4 c3 = *reinterpret_cast<const float4*>(Wd + d*384 + 256 + c0);
            sWS[d*129 + c0 + 0] = a.x + c3.x;
            sWS[d*129 + c0 + 1] = a.y + c3.y;
            sWS[d*129 + c0 + 2] = a.z + c3.z;
            sWS[d*129 + c0 + 3] = a.w + c3.w;
        }
    }

    // ---- Gram: G = X X^T, K=512 in 4 chunks, double-buffered S0/S1 <-> S2/S3 ----
    int cr = t >> 2, uh = (t & 3)*32;
    const float* xrow = infos + (((size_t)b*128 + cr)*16 + f)*512 + uh;
    float t2acc = 0.0f;
    float acc[2][4][4] = {};

    t2acc += fill_x(smc, 0, xrow, cr, uh);              // chunk 0 -> buf0 (S0/S1)
    __syncthreads();
    #pragma unroll
    for (int kk = 0; kk < 4; ++kk){
        if (kk < 3)
            t2acc += fill_x(smc, ((kk + 1) & 1) ? 2u*TILEB : 0u,
                            xrow + (kk + 1)*128, cr, uh);
        u32 off = (kk & 1) ? 2u*TILEB : 0u;
        gemm_tile(acc, aBase + off, aBase + off + TILEB, bBase + off, bBase + off + TILEB);
        __syncthreads();
    }
    // NOTE: S2/S3 now holds chunk 3 == output v-tile 3 (preserved below)
    atomicAdd(&sT2[cr], t2acc);
    __syncthreads();

    // ---- T1 epilogue from Gram accumulators (WS @ S4) ----
    {
        const float* sWS = reinterpret_cast<const float*>(smc + 4*TILEB);
        #pragma unroll
        for (int mi = 0; mi < 2; ++mi){
            int r0 = m0 + mi*16 + g, r1 = r0 + 8;
            float s0 = 0.0f, s1 = 0.0f;
            #pragma unroll
            for (int ni = 0; ni < 4; ++ni){
                int col = n0 + ni*8 + 2*t4;
                s0 += acc[mi][ni][0]*sWS[r0*129 + col] + acc[mi][ni][1]*sWS[r0*129 + col + 1];
                s1 += acc[mi][ni][2]*sWS[r1*129 + col] + acc[mi][ni][3]*sWS[r1*129 + col + 1];
            }
            atomicAdd(&sT1[r0], s0);
            atomicAdd(&sT1[r1], s1);
        }
    }
    __syncthreads();
    if (t < 128){
        float t1v = sT1[t], t2v = sT2[t];
        g_T1[bf*128 + t] = t1v;
        g_T2[bf*128 + t] = t2v;
        sVec[t] = t1v + t2v * bd[t];
    }
    __syncthreads();

    // ---- Wn tiles (hi@S0, lo@S1) + BQ [c][e] rows (hi@S4, lo@S5; WS dead) ----
    {
        int o = t >> 2, ch = (t & 3)*32;
        #pragma unroll
        for (int i = 0; i < 8; ++i){
            int c0 = ch + i*4;
            float4 w = *reinterpret_cast<const float4*>(Wn + o*128 + c0);
            u64 hv, lv; pack4(w, hv, lv);
            *reinterpret_cast<u64*>(smc + (o*ST + c0)*2)         = hv;
            *reinterpret_cast<u64*>(smc + TILEB + (o*ST + c0)*2) = lv;
        }
    }
    {
        int c = t >> 2, eb = (t & 3)*32;
        float t2c = sT2[c];
        #pragma unroll
        for (int i = 0; i < 8; ++i){
            int e0 = eb + i*4;
            float4 a  = *reinterpret_cast<const float4*>(Wd + c*384 + 128 + e0);
            float4 c3 = *reinterpret_cast<const float4*>(Wd + c*384 + 256 + e0);
            float4 v4 = make_float4(t2c*(a.x - c3.x), t2c*(a.y - c3.y), t2c*(a.z - c3.z), t2c*(a.w - c3.w));
            u64 hv, lv; pack4(v4, hv, lv);
            *reinterpret_cast<u64*>(smc + 4*TILEB + (c*ST + e0)*2) = hv;
            *reinterpret_cast<u64*>(smc + 5*TILEB + (c*ST + e0)*2) = lv;
        }
    }
    __syncthreads();

    // ---- k0[o] (t<128, from Wn smem) then Q gemm (all warps) ----
    float ksum = 0.0f;
    if (t < 128){
        #pragma unroll 4
        for (int c2 = 0; c2 < 128; c2 += 2){
            u32 hw = *reinterpret_cast<const u32*>(smc + (t*ST + c2)*2);
            u32 lw = *reinterpret_cast<const u32*>(smc + TILEB + (t*ST + c2)*2);
            float w0 = bf2f(hw & 0xffff) + bf2f(lw & 0xffff);
            float w1 = bf2f(hw >> 16)    + bf2f(lw >> 16);
            ksum += w0*sVec[c2] + w1*sVec[c2 + 1];
        }
    }
    float qacc[2][4][4] = {};
    gemm_tile_tb(qacc, aBase, aBase + TILEB, sb + 4*TILEB + bToff, sb + 5*TILEB + bToff);
    __syncthreads();

    // ---- Q epilogue: split to bf16 hi/lo straight into S0/S1 (overwrite Wn) ----
    #pragma unroll
    for (int mi = 0; mi < 2; ++mi){
        int r0 = m0 + mi*16 + g, r1 = r0 + 8;
        #pragma unroll
        for (int ni = 0; ni < 4; ++ni){
            int col = n0 + ni*8 + 2*t4;
            u32 h01, l01;
            split2(qacc[mi][ni][0], qacc[mi][ni][1], h01, l01);
            *reinterpret_cast<u32*>(smc + (r0*ST + col)*2)         = h01;
            *reinterpret_cast<u32*>(smc + TILEB + (r0*ST + col)*2) = l01;
            split2(qacc[mi][ni][2], qacc[mi][ni][3], h01, l01);
            *reinterpret_cast<u32*>(smc + (r1*ST + col)*2)         = h01;
            *reinterpret_cast<u32*>(smc + TILEB + (r1*ST + col)*2) = l01;
        }
    }
    if (t < 128) sBase[t] = ksum*(1.0f/512.0f) + bn[t];

    // prefetch vt0 for the output loop (S2/S3 already holds vt3)
    float4 pf[8];
    #pragma unroll
    for (int i = 0; i < 8; ++i) pf[i] = *reinterpret_cast<const float4*>(xrow + i*4);
    __syncthreads();

    // ---- output loop, tile order {3,0,1,2}, double-buffered S2/S3 <-> S4/S5 ----
    const float inv = 1.0f/512.0f;
    #pragma unroll
    for (int it = 0; it < 4; ++it){
        const int ord[4] = {3,0,1,2};
        int vt = ord[it];
        u32 curB = sb + (2 + 2*(it & 1))*TILEB + bToff;
        u32 othW = (2 + 2*((it + 1) & 1))*TILEB;
        if (it < 3){
            #pragma unroll
            for (int i = 0; i < 8; ++i){
                int vl = uh + i*4;
                u64 hv, lv; pack4(pf[i], hv, lv);
                *reinterpret_cast<u64*>(smc + othW + (cr*ST + vl)*2)         = hv;
                *reinterpret_cast<u64*>(smc + othW + TILEB + (cr*ST + vl)*2) = lv;
            }
            if (it < 2){
                #pragma unroll
                for (int i = 0; i < 8; ++i) pf[i] = *reinterpret_cast<const float4*>(xrow + ord[it+2]*128 + i*4);
            }
        }

        float acc2[2][4][4] = {};
        gemm_tile_tb(acc2, aBase, aBase + TILEB, curB, curB + TILEB);

        int v0 = vt*128;
        #pragma unroll
        for (int mi = 0; mi < 2; ++mi){
            int o0 = m0 + mi*16 + g, o1 = o0 + 8;
            size_t base0 = ((size_t)(b*128 + o0)*16 + f)*512 + v0;
            size_t base1 = ((size_t)(b*128 + o1)*16 + f)*512 + v0;
            #pragma unroll
            for (int ni = 0; ni < 4; ++ni){
                int vc = n0 + ni*8 + 2*t4;
                float2 r0v, r1v;
                r0v.x = fmaxf(fmaf(acc2[mi][ni][0], inv, sBase[o0]), 0.0f);
                r0v.y = fmaxf(fmaf(acc2[mi][ni][1], inv, sBase[o0]), 0.0f);
                r1v.x = fmaxf(fmaf(acc2[mi][ni][2], inv, sBase[o1]), 0.0f);
                r1v.y = fmaxf(fmaf(acc2[mi][ni][3], inv, sBase[o1]), 0.0f);
                *reinterpret_cast<float2*>(out + base0 + vc) = r0v;
                *reinterpret_cast<float2*>(out + base1 + vc) = r1v;
            }
        }
        __syncthreads();
    }
}

// -------- K4: exact recompute of zero-affected output columns --------
// No staging: warps read weight rows coalesced from gmem, butterfly-reduce.
__global__ void __launch_bounds__(256, 1) k4_fix(const float* __restrict__ infos,
                                                 const float* __restrict__ Wd,
                                                 const float* __restrict__ bd,
                                                 const float* __restrict__ Wn,
                                                 const float* __restrict__ bn,
                                                 float* __restrict__ out){
    int slot = blockIdx.x;          // 0..1
    int bf   = blockIdx.y;
    int b = bf >> 4, f = bf & 15;
    int g = (f == 0) ? 0 : ((f <= 11) ? 1 : 2);
    int bg = b*GG + g;
    int nz = g_znum[bg]; if (nz > ZCAP) nz = ZCAP;
    if (slot >= nz) return;

    int t = threadIdx.x;            // 256 = 8 warps
    int w = t >> 5, lane = t & 31;

    __shared__ float sXv[128], sAgg[128];
    __shared__ float sXu[16][128];
    __shared__ int   sUs[16];
    __shared__ int   sM;

    for (int i = slot; i < nz; i += 2){
        int vz = g_zlist[bg*ZCAP + i].y;
        bool dup = false;
        for (int jj = 0; jj < i; ++jj)
            if (g_zlist[bg*ZCAP + jj].y == vz){ dup = true; break; }
        if (dup) continue;

        if (t == 0){
            int m = 0;
            for (int jj = i; jj < nz; ++jj){
                int2 e2 = g_zlist[bg*ZCAP + jj];
                if (e2.y == vz && m < 16) sUs[m++] = e2.x;
            }
            sM = m;
        }
        __syncthreads();
        int m = sM;

        if (t < 128){
            sXv[t] = infos[(size_t)(b*2048 + t*16 + f)*512 + vz];
            for (int k = 0; k < m; ++k)
                sXu[k][t] = infos[(size_t)(b*2048 + t*16 + f)*512 + sUs[k]];
        }
        __syncthreads();

        // agg rows: warp w handles c = w*16 + r; lanes cover e (coalesced float4)
        #pragma unroll 2
        for (int r = 0; r < 16; ++r){
            int c = w*16 + r;
            float4 w1 = *reinterpret_cast<const float4*>(Wd + c*384 + lane*4);
            float4 w2 = *reinterpret_cast<const float4*>(Wd + c*384 + 128 + lane*4);
            float4 w3 = *reinterpret_cast<const float4*>(Wd + c*384 + 256 + lane*4);
            float ws0 = w1.x + w3.x, ws1 = w1.y + w3.y, ws2 = w1.z + w3.z, ws3 = w1.w + w3.w;
            float4 xv = *reinterpret_cast<const float4*>(&sXv[lane*4]);
            float dv = (w2.x - w3.x)*xv.x + (w2.y - w3.y)*xv.y
                     + (w2.z - w3.z)*xv.z + (w2.w - w3.w)*xv.w;
            dv = warp_sum(dv);

            float a1 = g_T1[bf*128 + c];
            float a2 = g_T2[bf*128 + c];
            for (int k = 0; k < m; ++k){
                float4 xu = *reinterpret_cast<const float4*>(&sXu[k][lane*4]);
                float su = ws0*xu.x + ws1*xu.y + ws2*xu.z + ws3*xu.w;
                su = warp_sum(su);
                float xuc = sXu[k][c];
                a1 -= xuc * su;
                a2 -= xuc;
            }
            if (lane == 0){
                int degi = 512 - g_zcnt[bg*512 + vz];
                float deg = (float)(degi > 1 ? degi : 1);
                sAgg[c] = (a1 + a2*(dv + bd[c])) / deg;
            }
        }
        __syncthreads();

        // output rows: warp w handles o = w*16 + r
        #pragma unroll 2
        for (int r = 0; r < 16; ++r){
            int o = w*16 + r;
            float4 wnv = *reinterpret_cast<const float4*>(Wn + o*128 + lane*4);
            float4 ag  = *reinterpret_cast<const float4*>(&sAgg[lane*4]);
            float s = wnv.x*ag.x + wnv.y*ag.y + wnv.z*ag.z + wnv.w*ag.w;
            s = warp_sum(s);
            if (lane == 0)
                out[(size_t)(b*2048 + o*16 + f)*512 + vz] = fmaxf(s + bn[o], 0.0f);
        }
        __syncthreads();
    }
}

extern "C" void kernel_launch(void* const* d_in, const int* in_sizes, int n_in,
                              void* d_out, int out_size){
    const float* Y     = (const float*)d_in[0];
    const float* infos = (const float*)d_in[1];
    const float* Wd    = (const float*)d_in[2];
    const float* bd    = (const float*)d_in[3];
    const float* Wn    = (const float*)d_in[4];
    const float* bn    = (const float*)d_in[5];
    float* out = (float*)d_out;

    cudaFuncSetAttribute(kfuse, cudaFuncAttributeMaxDynamicSharedMemorySize, DYNSM);

    kinit<<<16, 256>>>();
    kscan<<<6144, 256>>>(Y);
    kfuse<<<128, 512, DYNSM>>>(infos, Wd, bd, Wn, bn, out);
    k4_fix<<<dim3(2, 128), 256>>>(infos, Wd, bd, Wn, bn, out);
}

// round 14
// speedup vs baseline: 1.7207x; 1.0854x over previous
#include <cuda_runtime.h>
#include <cuda_bf16.h>
#include <cstdint>

typedef unsigned int u32;
typedef unsigned long long u64;
typedef unsigned short u16;

#define GG 3
#define ZCAP 4096
#define ST 136                 // bf16 elements per padded tile row (272 B)
#define TILEB (128*ST*2)       // 34816 bytes per 128x128 bf16 tile
#define DYNSM (6*TILEB)        // 208896

// ---------------- device scratch (allocation-free) ----------------
__device__ int   g_znum[24];
__device__ int   g_zcnt[24*512];
__device__ int2  g_zlist[24*ZCAP];

// ---------------- helpers ----------------
static __device__ __forceinline__ u32 smem_u32(const void* p){
    u32 a;
    asm("{ .reg .u64 t; cvta.to.shared.u64 t, %1; cvt.u32.u64 %0, t; }" : "=r"(a) : "l"(p));
    return a;
}
#define LDSM_X4(r, a) \
    asm volatile("ldmatrix.sync.aligned.m8n8.x4.shared.b16 {%0,%1,%2,%3}, [%4];" \
        : "=r"((r)[0]),"=r"((r)[1]),"=r"((r)[2]),"=r"((r)[3]) : "r"(a))
#define LDSM_X4_T(r, a) \
    asm volatile("ldmatrix.sync.aligned.m8n8.x4.trans.shared.b16 {%0,%1,%2,%3}, [%4];" \
        : "=r"((r)[0]),"=r"((r)[1]),"=r"((r)[2]),"=r"((r)[3]) : "r"(a))

static __device__ __forceinline__ void mma16816(float* c, const u32* a, const u32* b){
    asm volatile("mma.sync.aligned.m16n8k16.row.col.f32.bf16.bf16.f32 "
        "{%0,%1,%2,%3}, {%4,%5,%6,%7}, {%8,%9}, {%0,%1,%2,%3};"
        : "+f"(c[0]),"+f"(c[1]),"+f"(c[2]),"+f"(c[3])
        : "r"(a[0]),"r"(a[1]),"r"(a[2]),"r"(a[3]), "r"(b[0]),"r"(b[1]));
}
// truncation split of two floats: h = packed bf16 hi (exact truncation),
// l = packed bf16 of exact residuals. a -> low half, b -> high half.
static __device__ __forceinline__ void split2(float a, float b, u32& h, u32& l){
    u32 ua = __float_as_uint(a), ub = __float_as_uint(b);
    h = __byte_perm(ua, ub, 0x7632);
    float la = a - __uint_as_float(ua & 0xFFFF0000u);
    float lb = b - __uint_as_float(ub & 0xFFFF0000u);
    asm("cvt.rn.bf16x2.f32 %0, %1, %2;" : "=r"(l) : "f"(lb), "f"(la));
}
static __device__ __forceinline__ void pack4(float4 x, u64& hv, u64& lv){
    u32 h01, l01, h23, l23;
    split2(x.x, x.y, h01, l01);
    split2(x.z, x.w, h23, l23);
    hv = (u64)h01 | ((u64)h23 << 32);
    lv = (u64)l01 | ((u64)l23 << 32);
}
static __device__ __forceinline__ float bf2f(u32 bits16){ return __uint_as_float(bits16 << 16); }

static __device__ __forceinline__ float warp_sum(float v){
    #pragma unroll
    for (int off = 16; off; off >>= 1) v += __shfl_xor_sync(0xFFFFFFFFu, v, off);
    return v;
}

// fill one X chunk (hi/lo split) into a tile buffer; returns partial T2 sum
static __device__ __forceinline__ float fill_x(char* smc, u32 bufOff, const float* src,
                                               int cr, int uh){
    float t2 = 0.0f;
    #pragma unroll
    for (int i = 0; i < 8; ++i){
        int ul = uh + i*4;
        float4 x = *reinterpret_cast<const float4*>(src + i*4);
        t2 += x.x + x.y + x.z + x.w;
        u64 hv, lv; pack4(x, hv, lv);
        *reinterpret_cast<u64*>(smc + bufOff + (cr*ST + ul)*2)         = hv;
        *reinterpret_cast<u64*>(smc + bufOff + TILEB + (cr*ST + ul)*2) = lv;
    }
    return t2;
}

// non-trans gemm (A [m][k] rows, B [n][k] rows), 3 split products, warp 32x32 tile
static __device__ __forceinline__ void gemm_tile(float acc[2][4][4], u32 aH, u32 aL, u32 bH, u32 bL){
    #pragma unroll
    for (int ks = 0; ks < 8; ++ks){
        u32 ah[2][4], al[2][4], bh[2][4], bl[2][4];
        #pragma unroll
        for (int mi = 0; mi < 2; ++mi){
            LDSM_X4(ah[mi], aH + mi*(16*ST*2) + ks*32);
            LDSM_X4(al[mi], aL + mi*(16*ST*2) + ks*32);
        }
        #pragma unroll
        for (int nj = 0; nj < 2; ++nj){
            LDSM_X4(bh[nj], bH + nj*(16*ST*2) + ks*32);
            LDSM_X4(bl[nj], bL + nj*(16*ST*2) + ks*32);
        }
        #pragma unroll
        for (int mi = 0; mi < 2; ++mi)
        #pragma unroll
        for (int nj = 0; nj < 2; ++nj){
            mma16816(acc[mi][nj*2],   ah[mi], &bh[nj][0]);
            mma16816(acc[mi][nj*2+1], ah[mi], &bh[nj][2]);
        }
        #pragma unroll
        for (int mi = 0; mi < 2; ++mi)
        #pragma unroll
        for (int nj = 0; nj < 2; ++nj){
            mma16816(acc[mi][nj*2],   ah[mi], &bl[nj][0]);
            mma16816(acc[mi][nj*2+1], ah[mi], &bl[nj][2]);
        }
        #pragma unroll
        for (int mi = 0; mi < 2; ++mi)
        #pragma unroll
        for (int nj = 0; nj < 2; ++nj){
            mma16816(acc[mi][nj*2],   al[mi], &bh[nj][0]);
            mma16816(acc[mi][nj*2+1], al[mi], &bh[nj][2]);
        }
    }
}

// trans-B gemm (A [m][k] rows, B [k][n] rows via ldmatrix.trans)
static __device__ __forceinline__ void gemm_tile_tb(float acc[2][4][4], u32 aH, u32 aL, u32 bH, u32 bL){
    #pragma unroll
    for (int ks = 0; ks < 8; ++ks){
        u32 ah[2][4], al[2][4], bh[2][4], bl[2][4];
        #pragma unroll
        for (int mi = 0; mi < 2; ++mi){
            LDSM_X4(ah[mi], aH + mi*(16*ST*2) + ks*32);
            LDSM_X4(al[mi], aL + mi*(16*ST*2) + ks*32);
        }
        #pragma unroll
        for (int nj = 0; nj < 2; ++nj){
            LDSM_X4_T(bh[nj], bH + nj*32 + ks*(16*ST*2));
            LDSM_X4_T(bl[nj], bL + nj*32 + ks*(16*ST*2));
        }
        #pragma unroll
        for (int mi = 0; mi < 2; ++mi)
        #pragma unroll
        for (int nj = 0; nj < 2; ++nj){
            mma16816(acc[mi][nj*2],   ah[mi], &bh[nj][0]);
            mma16816(acc[mi][nj*2+1], ah[mi], &bh[nj][2]);
        }
        #pragma unroll
        for (int mi = 0; mi < 2; ++mi)
        #pragma unroll
        for (int nj = 0; nj < 2; ++nj){
            mma16816(acc[mi][nj*2],   ah[mi], &bl[nj][0]);
            mma16816(acc[mi][nj*2+1], ah[mi], &bl[nj][2]);
        }
        #pragma unroll
        for (int mi = 0; mi < 2; ++mi)
        #pragma unroll
        for (int nj = 0; nj < 2; ++nj){
            mma16816(acc[mi][nj*2],   al[mi], &bh[nj][0]);
            mma16816(acc[mi][nj*2+1], al[mi], &bh[nj][2]);
        }
    }
}

// -------- init --------
__global__ void kinit(){
    int t = blockIdx.x*blockDim.x + threadIdx.x;
    if (t < 24) g_znum[t] = 0;
    for (int i = t; i < 24*512; i += 16*256) g_zcnt[i] = 0;
}

// -------- scan Y slices 0..2 for exact zeros --------
__global__ void kscan(const float* __restrict__ Y){
    int gtid = blockIdx.x*blockDim.x + threadIdx.x;
    int bg   = gtid >> 16;
    int off4 = gtid & 65535;
    int b = bg / GG, g = bg % GG;
    const float4 y4 = reinterpret_cast<const float4*>(Y)[(size_t)(b*16 + g)*65536 + off4];
    int l = off4 * 4;
    int u = l >> 9, v = l & 511;
    float vals[4] = {y4.x, y4.y, y4.z, y4.w};
    #pragma unroll
    for (int r = 0; r < 4; ++r){
        if (vals[r] == 0.0f){
            int pos = atomicAdd(&g_znum[bg], 1);
            if (pos < ZCAP) g_zlist[bg*ZCAP + pos] = make_int2(u, v + r);
            atomicAdd(&g_zcnt[bg*512 + v + r], 1);
        }
    }
}

// -------- fused kernel: Gram -> T1/T2 -> Q -> output -> zero-fix, one CTA per (b,f) --------
__global__ void __launch_bounds__(512, 1) kfuse(const float* __restrict__ infos,
                                                const float* __restrict__ Wd,
                                                const float* __restrict__ bd,
                                                const float* __restrict__ Wn,
                                                const float* __restrict__ bn,
                                                float* __restrict__ out){
    extern __shared__ __align__(16) char smc[];
    __shared__ float sT1[128], sT2[128], sVec[128], sBase[128];
    __shared__ int   sUs[16];
    __shared__ int   sM;

    int bf = blockIdx.x, b = bf >> 4, f = bf & 15;
    int t = threadIdx.x, wid = t >> 5, lane = t & 31;
    int wm = wid & 3, wn = wid >> 2;
    int m0 = wm*32, n0 = wn*32;
    int g = lane >> 2, t4 = lane & 3;

    u32 sb = smem_u32(smc);
    u32 aBase = sb + (u32)(((m0 + (lane & 15))*ST + (lane >> 4)*8) * 2);
    u32 bBase = sb + (u32)(((n0 + (lane & 7) + ((lane >> 4) & 1)*8)*ST + ((lane >> 3) & 1)*8) * 2);
    u32 bToff = (u32)(((lane & 15)*ST + n0 + (lane >> 4)*8) * 2);

    if (t < 128){ sT1[t] = 0.0f; sT2[t] = 0.0f; }

    // ---- WS = W1+W3 fp32 [128][129] at S4 (untouched during Gram) ----
    {
        float* sWS = reinterpret_cast<float*>(smc + 4*TILEB);
        int d = t >> 2, ch = (t & 3)*32;
        #pragma unroll
        for (int i = 0; i < 8; ++i){
            int c0 = ch + i*4;
            float4 a  = *reinterpret_cast<const float4*>(Wd + d*384 + c0);
            float4 c3 = *reinterpret_cast<const float4*>(Wd + d*384 + 256 + c0);
            sWS[d*129 + c0 + 0] = a.x + c3.x;
            sWS[d*129 + c0 + 1] = a.y + c3.y;
            sWS[d*129 + c0 + 2] = a.z + c3.z;
            sWS[d*129 + c0 + 3] = a.w + c3.w;
        }
    }

    // ---- Gram: G = X X^T, K=512 in 4 chunks, double-buffered S0/S1 <-> S2/S3 ----
    int cr = t >> 2, uh = (t & 3)*32;
    const float* xrow = infos + (((size_t)b*128 + cr)*16 + f)*512 + uh;
    float t2acc = 0.0f;
    float acc[2][4][4] = {};

    t2acc += fill_x(smc, 0, xrow, cr, uh);              // chunk 0 -> buf0 (S0/S1)
    __syncthreads();
    #pragma unroll
    for (int kk = 0; kk < 4; ++kk){
        if (kk < 3)
            t2acc += fill_x(smc, ((kk + 1) & 1) ? 2u*TILEB : 0u,
                            xrow + (kk + 1)*128, cr, uh);
        u32 off = (kk & 1) ? 2u*TILEB : 0u;
        gemm_tile(acc, aBase + off, aBase + off + TILEB, bBase + off, bBase + off + TILEB);
        __syncthreads();
    }
    // NOTE: S2/S3 now holds chunk 3 == output v-tile 3 (preserved below)
    atomicAdd(&sT2[cr], t2acc);
    __syncthreads();

    // ---- T1 epilogue from Gram accumulators (WS @ S4) ----
    {
        const float* sWS = reinterpret_cast<const float*>(smc + 4*TILEB);
        #pragma unroll
        for (int mi = 0; mi < 2; ++mi){
            int r0 = m0 + mi*16 + g, r1 = r0 + 8;
            float s0 = 0.0f, s1 = 0.0f;
            #pragma unroll
            for (int ni = 0; ni < 4; ++ni){
                int col = n0 + ni*8 + 2*t4;
                s0 += acc[mi][ni][0]*sWS[r0*129 + col] + acc[mi][ni][1]*sWS[r0*129 + col + 1];
                s1 += acc[mi][ni][2]*sWS[r1*129 + col] + acc[mi][ni][3]*sWS[r1*129 + col + 1];
            }
            atomicAdd(&sT1[r0], s0);
            atomicAdd(&sT1[r1], s1);
        }
    }
    __syncthreads();
    if (t < 128) sVec[t] = sT1[t] + sT2[t] * bd[t];
    __syncthreads();

    // ---- Wn tiles (hi@S0, lo@S1) + BQ [c][e] rows (hi@S4, lo@S5; WS dead) ----
    {
        int o = t >> 2, ch = (t & 3)*32;
        #pragma unroll
        for (int i = 0; i < 8; ++i){
            int c0 = ch + i*4;
            float4 w = *reinterpret_cast<const float4*>(Wn + o*128 + c0);
            u64 hv, lv; pack4(w, hv, lv);
            *reinterpret_cast<u64*>(smc + (o*ST + c0)*2)         = hv;
            *reinterpret_cast<u64*>(smc + TILEB + (o*ST + c0)*2) = lv;
        }
    }
    {
        int c = t >> 2, eb = (t & 3)*32;
        float t2c = sT2[c];
        #pragma unroll
        for (int i = 0; i < 8; ++i){
            int e0 = eb + i*4;
            float4 a  = *reinterpret_cast<const float4*>(Wd + c*384 + 128 + e0);
            float4 c3 = *reinterpret_cast<const float4*>(Wd + c*384 + 256 + e0);
            float4 v4 = make_float4(t2c*(a.x - c3.x), t2c*(a.y - c3.y), t2c*(a.z - c3.z), t2c*(a.w - c3.w));
            u64 hv, lv; pack4(v4, hv, lv);
            *reinterpret_cast<u64*>(smc + 4*TILEB + (c*ST + e0)*2) = hv;
            *reinterpret_cast<u64*>(smc + 5*TILEB + (c*ST + e0)*2) = lv;
        }
    }
    __syncthreads();

    // ---- k0[o] (t<128, from Wn smem) then Q gemm (all warps) ----
    float ksum = 0.0f;
    if (t < 128){
        #pragma unroll 4
        for (int c2 = 0; c2 < 128; c2 += 2){
            u32 hw = *reinterpret_cast<const u32*>(smc + (t*ST + c2)*2);
            u32 lw = *reinterpret_cast<const u32*>(smc + TILEB + (t*ST + c2)*2);
            float w0 = bf2f(hw & 0xffff) + bf2f(lw & 0xffff);
            float w1 = bf2f(hw >> 16)    + bf2f(lw >> 16);
            ksum += w0*sVec[c2] + w1*sVec[c2 + 1];
        }
    }
    float qacc[2][4][4] = {};
    gemm_tile_tb(qacc, aBase, aBase + TILEB, sb + 4*TILEB + bToff, sb + 5*TILEB + bToff);
    __syncthreads();

    // ---- Q epilogue: split to bf16 hi/lo straight into S0/S1 (overwrite Wn) ----
    #pragma unroll
    for (int mi = 0; mi < 2; ++mi){
        int r0 = m0 + mi*16 + g, r1 = r0 + 8;
        #pragma unroll
        for (int ni = 0; ni < 4; ++ni){
            int col = n0 + ni*8 + 2*t4;
            u32 h01, l01;
            split2(qacc[mi][ni][0], qacc[mi][ni][1], h01, l01);
            *reinterpret_cast<u32*>(smc + (r0*ST + col)*2)         = h01;
            *reinterpret_cast<u32*>(smc + TILEB + (r0*ST + col)*2) = l01;
            split2(qacc[mi][ni][2], qacc[mi][ni][3], h01, l01);
            *reinterpret_cast<u32*>(smc + (r1*ST + col)*2)         = h01;
            *reinterpret_cast<u32*>(smc + TILEB + (r1*ST + col)*2) = l01;
        }
    }
    if (t < 128) sBase[t] = ksum*(1.0f/512.0f) + bn[t];

    // prefetch vt0 for the output loop (S2/S3 already holds vt3)
    float4 pf[8];
    #pragma unroll
    for (int i = 0; i < 8; ++i) pf[i] = *reinterpret_cast<const float4*>(xrow + i*4);
    __syncthreads();

    // ---- output loop, tile order {3,0,1,2}, double-buffered S2/S3 <-> S4/S5 ----
    const float inv = 1.0f/512.0f;
    #pragma unroll
    for (int it = 0; it < 4; ++it){
        const int ord[4] = {3,0,1,2};
        int vt = ord[it];
        u32 curB = sb + (2 + 2*(it & 1))*TILEB + bToff;
        u32 othW = (2 + 2*((it + 1) & 1))*TILEB;
        if (it < 3){
            #pragma unroll
            for (int i = 0; i < 8; ++i){
                int vl = uh + i*4;
                u64 hv, lv; pack4(pf[i], hv, lv);
                *reinterpret_cast<u64*>(smc + othW + (cr*ST + vl)*2)         = hv;
                *reinterpret_cast<u64*>(smc + othW + TILEB + (cr*ST + vl)*2) = lv;
            }
            if (it < 2){
                #pragma unroll
                for (int i = 0; i < 8; ++i) pf[i] = *reinterpret_cast<const float4*>(xrow + ord[it+2]*128 + i*4);
            }
        }

        float acc2[2][4][4] = {};
        gemm_tile_tb(acc2, aBase, aBase + TILEB, curB, curB + TILEB);

        int v0 = vt*128;
        #pragma unroll
        for (int mi = 0; mi < 2; ++mi){
            int o0 = m0 + mi*16 + g, o1 = o0 + 8;
            size_t base0 = ((size_t)(b*128 + o0)*16 + f)*512 + v0;
            size_t base1 = ((size_t)(b*128 + o1)*16 + f)*512 + v0;
            #pragma unroll
            for (int ni = 0; ni < 4; ++ni){
                int vc = n0 + ni*8 + 2*t4;
                float2 r0v, r1v;
                r0v.x = fmaxf(fmaf(acc2[mi][ni][0], inv, sBase[o0]), 0.0f);
                r0v.y = fmaxf(fmaf(acc2[mi][ni][1], inv, sBase[o0]), 0.0f);
                r1v.x = fmaxf(fmaf(acc2[mi][ni][2], inv, sBase[o1]), 0.0f);
                r1v.y = fmaxf(fmaf(acc2[mi][ni][3], inv, sBase[o1]), 0.0f);
                *reinterpret_cast<float2*>(out + base0 + vc) = r0v;
                *reinterpret_cast<float2*>(out + base1 + vc) = r1v;
            }
        }
        __syncthreads();
    }

    // ---- tail: exact fix of zero-affected columns for this (b,f); weights L2-hot ----
    {
        int gz = (f == 0) ? 0 : ((f <= 11) ? 1 : 2);
        int bg = b*GG + gz;
        int nz = g_znum[bg]; if (nz > ZCAP) nz = ZCAP;
        if (nz > 0){
            float* sXv  = reinterpret_cast<float*>(smc);          // Q region dead
            float* sAgg = sXv + 128;
            float* sXu  = sAgg + 128;                              // [16][128]

            for (int i = 0; i < nz; ++i){
                int vz = g_zlist[bg*ZCAP + i].y;
                bool dup = false;
                for (int jj = 0; jj < i; ++jj)
                    if (g_zlist[bg*ZCAP + jj].y == vz){ dup = true; break; }
                if (dup) continue;

                if (t == 0){
                    int m = 0;
                    for (int jj = i; jj < nz; ++jj){
                        int2 e2 = g_zlist[bg*ZCAP + jj];
                        if (e2.y == vz && m < 16) sUs[m++] = e2.x;
                    }
                    sM = m;
                }
                __syncthreads();
                int m = sM;

                if (t < 128){
                    sXv[t] = infos[(size_t)(b*2048 + t*16 + f)*512 + vz];
                    for (int k = 0; k < m; ++k)
                        sXu[k*128 + t] = infos[(size_t)(b*2048 + t*16 + f)*512 + sUs[k]];
                }
                __syncthreads();

                // agg rows: 16 warps x 8 rows; lanes cover e (coalesced float4, L2-hot)
                #pragma unroll 2
                for (int r = 0; r < 8; ++r){
                    int c = wid*8 + r;
                    float4 w1 = *reinterpret_cast<const float4*>(Wd + c*384 + lane*4);
                    float4 w2 = *reinterpret_cast<const float4*>(Wd + c*384 + 128 + lane*4);
                    float4 w3 = *reinterpret_cast<const float4*>(Wd + c*384 + 256 + lane*4);
                    float ws0 = w1.x + w3.x, ws1 = w1.y + w3.y, ws2 = w1.z + w3.z, ws3 = w1.w + w3.w;
                    float4 xv = *reinterpret_cast<const float4*>(&sXv[lane*4]);
                    float dv = (w2.x - w3.x)*xv.x + (w2.y - w3.y)*xv.y
                             + (w2.z - w3.z)*xv.z + (w2.w - w3.w)*xv.w;
                    dv = warp_sum(dv);

                    float a1 = sT1[c];
                    float a2 = sT2[c];
                    for (int k = 0; k < m; ++k){
                        float4 xu = *reinterpret_cast<const float4*>(&sXu[k*128 + lane*4]);
                        float su = ws0*xu.x + ws1*xu.y + ws2*xu.z + ws3*xu.w;
                        su = warp_sum(su);
                        float xuc = sXu[k*128 + c];
                        a1 -= xuc * su;
                        a2 -= xuc;
                    }
                    if (lane == 0){
                        int degi = 512 - g_zcnt[bg*512 + vz];
                        float deg = (float)(degi > 1 ? degi : 1);
                        sAgg[c] = (a1 + a2*(dv + bd[c])) / deg;
                    }
                }
                __syncthreads();

                // output rows: 16 warps x 8 rows
                #pragma unroll 2
                for (int r = 0; r < 8; ++r){
                    int o = wid*8 + r;
                    float4 wnv = *reinterpret_cast<const float4*>(Wn + o*128 + lane*4);
                    float4 ag  = *reinterpret_cast<const float4*>(&sAgg[lane*4]);
                    float s = wnv.x*ag.x + wnv.y*ag.y + wnv.z*ag.z + wnv.w*ag.w;
                    s = warp_sum(s);
                    if (lane == 0)
                        out[(size_t)(b*2048 + o*16 + f)*512 + vz] = fmaxf(s + bn[o], 0.0f);
                }
                __syncthreads();
            }
        }
    }
}

extern "C" void kernel_launch(void* const* d_in, const int* in_sizes, int n_in,
                              void* d_out, int out_size){
    const float* Y     = (const float*)d_in[0];
    const float* infos = (const float*)d_in[1];
    const float* Wd    = (const float*)d_in[2];
    const float* bd    = (const float*)d_in[3];
    const float* Wn    = (const float*)d_in[4];
    const float* bn    = (const float*)d_in[5];
    float* out = (float*)d_out;

    cudaFuncSetAttribute(kfuse, cudaFuncAttributeMaxDynamicSharedMemorySize, DYNSM);

    kinit<<<16, 256>>>();
    kscan<<<6144, 256>>>(Y);
    kfuse<<<128, 512, DYNSM>>>(infos, Wd, bd, Wn, bn, out);
}